// round 8
// baseline (speedup 1.0000x reference)
#include <cuda_runtime.h>
#include <cuda_bf16.h>
#include <cstdint>

// Problem constants
#define DIMD 1024
#define NHEADS 16
#define HDIM 64
#define ROTD 32
#define BB 2
#define TT 32
#define HH 18
#define WW 32
#define NTOK (BB*TT*HH*WW)        // 36864
#define E3 (3*NHEADS*HDIM)        // 3072
#define TOK_TSTRIDE (HH*WW)       // 576

// Scratch (__device__ globals; allocation-free rule)
__device__ float g_qkv[(size_t)NTOK * E3];     // fp32 qkv (attention input)
__device__ float g_o[(size_t)NTOK * DIMD];     // attention output fp32

// ---------------------------------------------------------------------------
// Helpers
// ---------------------------------------------------------------------------
__device__ __forceinline__ uint32_t smem_u32(const void* p) {
    uint32_t a;
    asm("{ .reg .u64 t; cvta.to.shared.u64 t, %1; cvt.u32.u64 %0, t; }" : "=r"(a) : "l"(p));
    return a;
}
__device__ __forceinline__ uint32_t f2tf32(float f) {
    uint32_t r;
    asm("cvt.rna.tf32.f32 %0, %1;" : "=r"(r) : "f"(f));
    return r;
}
__device__ __forceinline__ void cp16(uint32_t saddr, const void* gaddr) {
    asm volatile("cp.async.cg.shared.global [%0], [%1], 16;" :: "r"(saddr), "l"(gaddr));
}
__device__ __forceinline__ void cp_commit() {
    asm volatile("cp.async.commit_group;" ::: "memory");
}
template <int N>
__device__ __forceinline__ void cp_wait() {
    asm volatile("cp.async.wait_group %0;" :: "n"(N) : "memory");
}
__device__ __forceinline__ void ldsm4(uint32_t* r, uint32_t addr) {
    asm volatile("ldmatrix.sync.aligned.m8n8.x4.shared.b16 {%0,%1,%2,%3}, [%4];"
                 : "=r"(r[0]), "=r"(r[1]), "=r"(r[2]), "=r"(r[3]) : "r"(addr));
}
__device__ __forceinline__ void mma_tf32(float c[4],
                                         const uint32_t a[4], const uint32_t b[2]) {
    asm volatile(
        "mma.sync.aligned.m16n8k8.row.col.f32.tf32.tf32.f32 "
        "{%0,%1,%2,%3}, {%4,%5,%6,%7}, {%8,%9}, {%0,%1,%2,%3};"
        : "+f"(c[0]), "+f"(c[1]), "+f"(c[2]), "+f"(c[3])
        : "r"(a[0]), "r"(a[1]), "r"(a[2]), "r"(a[3]), "r"(b[0]), "r"(b[1]));
}

// ---------------------------------------------------------------------------
// TF32 GEMM: C[M,N] = A[M,K] * B[N,K]^T (+bias). A,B are fp32; conversion to
// tf32 (rna) happens in registers after ldmatrix.
// CTA 128x128, BK=32, 128 threads (4 warps, 64x64 warp tile),
// 3-stage cp.async pipeline, fragment double-buffering, m16n8k8 tf32 mma.
// ---------------------------------------------------------------------------
#define NSTAGE 3
#define LDSK 36                          // u32 row stride (32 data + 4 pad)
#define STAGE_U32 (128 * LDSK)
#define STAGE_BYTES (STAGE_U32 * 4)      // 18432
#define PAIR_BYTES (2 * STAGE_BYTES)     // 36864
#define GSMEM_BYTES (NSTAGE * PAIR_BYTES) // 110592

__global__ __launch_bounds__(128, 2) void gemm_tf32(
    const float* __restrict__ A, const float* __restrict__ B,
    const float* __restrict__ bias, float* __restrict__ C,
    int M, int N, int K)
{
    extern __shared__ uint32_t sm_[];
    const uint32_t sbase = smem_u32(sm_);

    const int tid = threadIdx.x;
    const int wid = tid >> 5;
    const int lid = tid & 31;
    const int g   = lid >> 2;
    const int tig = lid & 3;
    const int wm  = (wid >> 1) * 64;
    const int wn  = (wid & 1) * 64;
    const int m0 = blockIdx.y * 128;
    const int n0 = blockIdx.x * 128;

    const int K4 = K >> 2;
    const uint4* A4 = (const uint4*)A;
    const uint4* B4 = (const uint4*)B;

    // Loader mapping: chunk i = tid + j*128 -> row = i>>3, kc4 = i&7
    const int lsub = tid >> 3;   // 0..15
    const int lkc4 = tid & 7;

    // Fragment lane offsets (u32 units within a stage matrix)
    const int a_lane = ((lid & 7) + ((lid >> 3) & 1) * 8) * LDSK + ((lid >> 4) & 1) * 4;
    const int b_lane = ((lid & 7) + ((lid >> 4) & 1) * 8) * LDSK + ((lid >> 3) & 1) * 4;
    const uint32_t aoff = (uint32_t)(wm * LDSK + a_lane) * 4;  // bytes
    const uint32_t boff = (uint32_t)(wn * LDSK + b_lane) * 4;

    float acc[4][8][4];
#pragma unroll
    for (int mt = 0; mt < 4; mt++)
#pragma unroll
        for (int nt = 0; nt < 8; nt++)
#pragma unroll
            for (int e = 0; e < 4; e++) acc[mt][nt][e] = 0.f;

    // Double-buffered fragments (raw bits until cvt)
    uint32_t af[2][4][4];
    uint32_t bf[2][8][2];

    const int NC = K >> 5;   // K/32

    auto load_stage = [&](int s, int c) {
        const uint32_t abase = sbase + s * PAIR_BYTES;
        const uint32_t bbase = abase + STAGE_BYTES;
        const int kb4 = c * 8;
#pragma unroll
        for (int j = 0; j < 8; j++) {
            const int row = j * 16 + lsub;
            const uint32_t soff = (uint32_t)(row * LDSK + lkc4 * 4) * 4;
            cp16(abase + soff, A4 + (size_t)(m0 + row) * K4 + kb4 + lkc4);
            cp16(bbase + soff, B4 + (size_t)(n0 + row) * K4 + kb4 + lkc4);
        }
    };

    // Prologue: NSTAGE-1 stages in flight
    load_stage(0, 0);
    cp_commit();
    load_stage(1, 1);
    cp_commit();

    for (int c = 0; c < NC; c++) {
        cp_wait<1>();
        __syncthreads();   // stage c resident; buffer (c-1)%3 free for reload

        if (c + 2 < NC) load_stage((c + 2) % NSTAGE, c + 2);
        cp_commit();

        const uint32_t abase = sbase + (c % NSTAGE) * PAIR_BYTES;
        const uint32_t bbase = abase + STAGE_BYTES;

        // ---- fragment prologue: kk=0 into buffer 0 ----
#pragma unroll
        for (int mt = 0; mt < 4; mt++)
            ldsm4(af[0][mt], abase + aoff + (uint32_t)(mt * 16 * LDSK) * 4);
#pragma unroll
        for (int p = 0; p < 4; p++)
            ldsm4(&bf[0][2 * p][0], bbase + boff + (uint32_t)(p * 16 * LDSK) * 4);
#pragma unroll
        for (int mt = 0; mt < 4; mt++)
#pragma unroll
            for (int i = 0; i < 4; i++)
                af[0][mt][i] = f2tf32(__uint_as_float(af[0][mt][i]));
#pragma unroll
        for (int nt = 0; nt < 8; nt++)
#pragma unroll
            for (int i = 0; i < 2; i++)
                bf[0][nt][i] = f2tf32(__uint_as_float(bf[0][nt][i]));

#pragma unroll
        for (int kk = 0; kk < 32; kk += 8) {
            const int cur = (kk >> 3) & 1;
            const int nxt = cur ^ 1;

            // 1) issue LDSMs for next kk-step (latency hides under MMAs)
            if (kk < 24) {
#pragma unroll
                for (int mt = 0; mt < 4; mt++)
                    ldsm4(af[nxt][mt], abase + aoff + (uint32_t)(mt * 16 * LDSK + kk + 8) * 4);
#pragma unroll
                for (int p = 0; p < 4; p++)
                    ldsm4(&bf[nxt][2 * p][0], bbase + boff + (uint32_t)(p * 16 * LDSK + kk + 8) * 4);
            }

            // 2) MMAs on current (already converted) fragments
#pragma unroll
            for (int mt = 0; mt < 4; mt++)
#pragma unroll
                for (int nt = 0; nt < 8; nt++)
                    mma_tf32(acc[mt][nt], af[cur][mt], bf[cur][nt]);

            // 3) convert next fragments (LDSM latency absorbed by MMA block)
            if (kk < 24) {
#pragma unroll
                for (int mt = 0; mt < 4; mt++)
#pragma unroll
                    for (int i = 0; i < 4; i++)
                        af[nxt][mt][i] = f2tf32(__uint_as_float(af[nxt][mt][i]));
#pragma unroll
                for (int nt = 0; nt < 8; nt++)
#pragma unroll
                    for (int i = 0; i < 2; i++)
                        bf[nxt][nt][i] = f2tf32(__uint_as_float(bf[nxt][nt][i]));
            }
        }
    }

    // Epilogue
#pragma unroll
    for (int mt = 0; mt < 4; mt++) {
        const int r = m0 + wm + mt * 16 + g;
#pragma unroll
        for (int nt = 0; nt < 8; nt++) {
            const int ccol = n0 + wn + nt * 8 + tig * 2;
            float b0v = 0.f, b1v = 0.f;
            if (bias) { b0v = __ldg(bias + ccol); b1v = __ldg(bias + ccol + 1); }
            float2 v;
            v.x = acc[mt][nt][0] + b0v;
            v.y = acc[mt][nt][1] + b1v;
            *(float2*)&C[(size_t)r * N + ccol] = v;
            v.x = acc[mt][nt][2] + b0v;
            v.y = acc[mt][nt][3] + b1v;
            *(float2*)&C[(size_t)(r + 8) * N + ccol] = v;
        }
    }
}

// ---------------------------------------------------------------------------
// Attention: one block per (sequence, head). Register-blocked S and O loops,
// causal work skipping.
// ---------------------------------------------------------------------------
__global__ __launch_bounds__(128) void attn_kernel(
    const float* __restrict__ qkv, float* __restrict__ o)
{
    const int nh = blockIdx.x;
    const int head = nh & (NHEADS - 1);
    const int seq = nh >> 4;
    const int w_ = seq % WW;
    const int h_ = (seq / WW) % HH;
    const int b_ = seq / (WW * HH);
    const int base = ((b_ * TT) * HH + h_) * WW + w_;

    __shared__ float Q[32][65];
    __shared__ float K[32][65];
    __shared__ float V[32][65];
    __shared__ float S[32][33];

    const int tid = threadIdx.x;

    for (int idx = tid; idx < 32 * 64; idx += 128) {
        int t = idx >> 6;
        int d = idx & 63;
        size_t off = (size_t)(base + t * TOK_TSTRIDE) * E3 + head * HDIM + d;
        Q[t][d] = qkv[off];
        K[t][d] = qkv[off + NHEADS * HDIM];
        V[t][d] = qkv[off + 2 * NHEADS * HDIM];
    }
    __syncthreads();

    // RoPE on first ROTD dims (interleaved pairs)
    const float LOG2_10000_OVER_16 = 13.287712379549449f / 16.0f;
    for (int idx = tid; idx < 32 * (ROTD / 2); idx += 128) {
        int t = idx >> 4;
        int j = idx & 15;
        float freq = exp2f(-(float)j * LOG2_10000_OVER_16);
        float ang = (float)t * freq;
        float c = cosf(ang), s = sinf(ang);
        float q0 = Q[t][2 * j], q1 = Q[t][2 * j + 1];
        Q[t][2 * j]     = q0 * c - q1 * s;
        Q[t][2 * j + 1] = q1 * c + q0 * s;
        float k0 = K[t][2 * j], k1 = K[t][2 * j + 1];
        K[t][2 * j]     = k0 * c - k1 * s;
        K[t][2 * j + 1] = k1 * c + k0 * s;
    }
    __syncthreads();

    // Scores: each thread computes a 2(tq) x 4(tk) block; skip fully-masked blocks
    {
        const int tq0 = (tid >> 3) * 2;   // 0,2,..,30
        const int tk0 = (tid & 7) * 4;    // 0,4,..,28
        if (tk0 <= tq0 + 1) {
            float s0[4] = {0.f, 0.f, 0.f, 0.f};
            float s1[4] = {0.f, 0.f, 0.f, 0.f};
#pragma unroll 8
            for (int d = 0; d < 64; d++) {
                float q0 = Q[tq0][d], q1 = Q[tq0 + 1][d];
#pragma unroll
                for (int j = 0; j < 4; j++) {
                    float kv = K[tk0 + j][d];
                    s0[j] = fmaf(q0, kv, s0[j]);
                    s1[j] = fmaf(q1, kv, s1[j]);
                }
            }
#pragma unroll
            for (int j = 0; j < 4; j++) {
                S[tq0][tk0 + j]     = s0[j] * 0.125f;
                S[tq0 + 1][tk0 + j] = s1[j] * 0.125f;
            }
        }
    }
    __syncthreads();

    // Causal softmax per row
    if (tid < 32) {
        int row = tid;
        float m = -1e30f;
        for (int k = 0; k <= row; k++) m = fmaxf(m, S[row][k]);
        float sum = 0.f;
        for (int k = 0; k <= row; k++) {
            float e = __expf(S[row][k] - m);
            S[row][k] = e;
            sum += e;
        }
        float inv = 1.0f / sum;
        for (int k = 0; k < 32; k++)
            S[row][k] = (k <= row) ? S[row][k] * inv : 0.f;
    }
    __syncthreads();

    // O = P V: each thread computes 2(t) x 8(d); k loop bounded by causality
    {
        const int t0 = (tid >> 3) * 2;    // 0,2,..,30
        const int d0 = (tid & 7) * 8;     // 0,8,..,56
        float a0[8], a1[8];
#pragma unroll
        for (int j = 0; j < 8; j++) { a0[j] = 0.f; a1[j] = 0.f; }
        const int kmax = t0 + 1;          // S[t0][t0+1] == 0, so exact
        for (int k = 0; k <= kmax; k++) {
            float p0 = S[t0][k], p1 = S[t0 + 1][k];
#pragma unroll
            for (int j = 0; j < 8; j++) {
                float vv = V[k][d0 + j];
                a0[j] = fmaf(p0, vv, a0[j]);
                a1[j] = fmaf(p1, vv, a1[j]);
            }
        }
        float* orow0 = o + (size_t)(base + t0 * TOK_TSTRIDE) * DIMD + head * HDIM + d0;
        float* orow1 = o + (size_t)(base + (t0 + 1) * TOK_TSTRIDE) * DIMD + head * HDIM + d0;
#pragma unroll
        for (int j = 0; j < 8; j++) { orow0[j] = a0[j]; orow1[j] = a1[j]; }
    }
}

// ---------------------------------------------------------------------------
// Launch
// ---------------------------------------------------------------------------
extern "C" void kernel_launch(void* const* d_in, const int* in_sizes, int n_in,
                              void* d_out, int out_size)
{
    const float* x     = (const float*)d_in[0];   // [NTOK, 1024]
    const float* w_qkv = (const float*)d_in[1];   // [3072, 1024]
    const float* w_out = (const float*)d_in[2];   // [1024, 1024]
    const float* b_out = (const float*)d_in[3];   // [1024]
    float* out = (float*)d_out;                   // [NTOK, 1024]

    float* qkv; float* o;
    cudaGetSymbolAddress((void**)&qkv, g_qkv);
    cudaGetSymbolAddress((void**)&o,   g_o);

    cudaFuncSetAttribute(gemm_tf32, cudaFuncAttributeMaxDynamicSharedMemorySize, GSMEM_BYTES);

    // 1) QKV projection: [36864,1024] x [3072,1024]^T -> [36864,3072]
    {
        dim3 grid(E3 / 128, NTOK / 128);
        gemm_tf32<<<grid, 128, GSMEM_BYTES>>>(x, w_qkv, nullptr, qkv, NTOK, E3, DIMD);
    }

    // 2) Attention
    {
        int nblocks = (BB * HH * WW) * NHEADS;   // 18432
        attn_kernel<<<nblocks, 128>>>(qkv, o);
    }

    // 3) Output projection: [36864,1024] x [1024,1024]^T + bias
    {
        dim3 grid(DIMD / 128, NTOK / 128);
        gemm_tf32<<<grid, 128, GSMEM_BYTES>>>(o, w_out, b_out, out, NTOK, DIMD, DIMD);
    }
}

// round 9
// speedup vs baseline: 1.0631x; 1.0631x over previous
#include <cuda_runtime.h>
#include <cuda_bf16.h>
#include <cstdint>

// Problem constants
#define DIMD 1024
#define NHEADS 16
#define HDIM 64
#define ROTD 32
#define BB 2
#define TT 32
#define HH 18
#define WW 32
#define NTOK (BB*TT*HH*WW)        // 36864
#define E3 (3*NHEADS*HDIM)        // 3072
#define TOK_TSTRIDE (HH*WW)       // 576

// Scratch (__device__ globals; allocation-free rule)
__device__ float    g_qkv[(size_t)NTOK * E3];     // fp32 qkv (attention input)
__device__ uint32_t g_o[(size_t)NTOK * DIMD];     // attention output, tf32 bits
__device__ uint32_t g_xt[(size_t)NTOK * DIMD];    // x as tf32 bits
__device__ uint32_t g_wqt[(size_t)E3 * DIMD];     // w_qkv tf32 bits
__device__ uint32_t g_wot[(size_t)DIMD * DIMD];   // w_out tf32 bits

// ---------------------------------------------------------------------------
// Helpers
// ---------------------------------------------------------------------------
__device__ __forceinline__ uint32_t smem_u32(const void* p) {
    uint32_t a;
    asm("{ .reg .u64 t; cvta.to.shared.u64 t, %1; cvt.u32.u64 %0, t; }" : "=r"(a) : "l"(p));
    return a;
}
__device__ __forceinline__ uint32_t f2tf32(float f) {
    uint32_t r;
    asm("cvt.rna.tf32.f32 %0, %1;" : "=r"(r) : "f"(f));
    return r;
}
__device__ __forceinline__ void cp16(uint32_t saddr, const void* gaddr) {
    asm volatile("cp.async.cg.shared.global [%0], [%1], 16;" :: "r"(saddr), "l"(gaddr));
}
__device__ __forceinline__ void cp_commit() {
    asm volatile("cp.async.commit_group;" ::: "memory");
}
template <int N>
__device__ __forceinline__ void cp_wait() {
    asm volatile("cp.async.wait_group %0;" :: "n"(N) : "memory");
}
__device__ __forceinline__ void ldsm4(uint32_t* r, uint32_t addr) {
    asm volatile("ldmatrix.sync.aligned.m8n8.x4.shared.b16 {%0,%1,%2,%3}, [%4];"
                 : "=r"(r[0]), "=r"(r[1]), "=r"(r[2]), "=r"(r[3]) : "r"(addr));
}
__device__ __forceinline__ void mma_tf32(float c[4],
                                         const uint32_t a[4], const uint32_t b[2]) {
    asm volatile(
        "mma.sync.aligned.m16n8k8.row.col.f32.tf32.tf32.f32 "
        "{%0,%1,%2,%3}, {%4,%5,%6,%7}, {%8,%9}, {%0,%1,%2,%3};"
        : "+f"(c[0]), "+f"(c[1]), "+f"(c[2]), "+f"(c[3])
        : "r"(a[0]), "r"(a[1]), "r"(a[2]), "r"(a[3]), "r"(b[0]), "r"(b[1]));
}

// ---------------------------------------------------------------------------
// fp32 -> tf32 bits (rna), elementwise. n in float4 units.
// ---------------------------------------------------------------------------
__global__ __launch_bounds__(256) void cvt_tf32(const float4* __restrict__ in,
                                                uint4* __restrict__ out, int n4)
{
    int i = blockIdx.x * 256 + threadIdx.x;
    if (i < n4) {
        float4 v = in[i];
        uint4 o;
        o.x = f2tf32(v.x); o.y = f2tf32(v.y); o.z = f2tf32(v.z); o.w = f2tf32(v.w);
        out[i] = o;
    }
}

// ---------------------------------------------------------------------------
// TF32 GEMM: C[M,N] = A[M,K] * B[N,K]^T (+bias). A,B hold tf32 bits.
// CTA 128x128, BK=32, 128 threads (4 warps, 64x64 warp tile),
// 3-stage cp.async pipeline + fragment double-buffering (no cvt in loop).
// ---------------------------------------------------------------------------
#define NSTAGE 3
#define LDSK 36                          // u32 row stride (32 data + 4 pad)
#define STAGE_U32 (128 * LDSK)
#define STAGE_BYTES (STAGE_U32 * 4)      // 18432
#define PAIR_BYTES (2 * STAGE_BYTES)     // 36864
#define GSMEM_BYTES (NSTAGE * PAIR_BYTES) // 110592

__global__ __launch_bounds__(128, 2) void gemm_tf32(
    const uint32_t* __restrict__ A, const uint32_t* __restrict__ B,
    const float* __restrict__ bias, float* __restrict__ C,
    int M, int N, int K)
{
    extern __shared__ uint32_t sm_[];
    const uint32_t sbase = smem_u32(sm_);

    const int tid = threadIdx.x;
    const int wid = tid >> 5;
    const int lid = tid & 31;
    const int g   = lid >> 2;
    const int tig = lid & 3;
    const int wm  = (wid >> 1) * 64;
    const int wn  = (wid & 1) * 64;
    const int m0 = blockIdx.y * 128;
    const int n0 = blockIdx.x * 128;

    const int K4 = K >> 2;
    const uint4* A4 = (const uint4*)A;
    const uint4* B4 = (const uint4*)B;

    // Loader mapping
    const int lsub = tid >> 3;   // 0..15
    const int lkc4 = tid & 7;

    // Fragment lane offsets (bytes within a stage matrix)
    const int a_lane = ((lid & 7) + ((lid >> 3) & 1) * 8) * LDSK + ((lid >> 4) & 1) * 4;
    const int b_lane = ((lid & 7) + ((lid >> 4) & 1) * 8) * LDSK + ((lid >> 3) & 1) * 4;
    const uint32_t aoff = (uint32_t)(wm * LDSK + a_lane) * 4;
    const uint32_t boff = (uint32_t)(wn * LDSK + b_lane) * 4;

    float acc[4][8][4];
#pragma unroll
    for (int mt = 0; mt < 4; mt++)
#pragma unroll
        for (int nt = 0; nt < 8; nt++)
#pragma unroll
            for (int e = 0; e < 4; e++) acc[mt][nt][e] = 0.f;

    uint32_t af[2][4][4];
    uint32_t bf[2][8][2];

    const int NC = K >> 5;

    auto load_stage = [&](int s, int c) {
        const uint32_t abase = sbase + s * PAIR_BYTES;
        const uint32_t bbase = abase + STAGE_BYTES;
        const int kb4 = c * 8;
#pragma unroll
        for (int j = 0; j < 8; j++) {
            const int row = j * 16 + lsub;
            const uint32_t soff = (uint32_t)(row * LDSK + lkc4 * 4) * 4;
            cp16(abase + soff, A4 + (size_t)(m0 + row) * K4 + kb4 + lkc4);
            cp16(bbase + soff, B4 + (size_t)(n0 + row) * K4 + kb4 + lkc4);
        }
    };

    load_stage(0, 0);
    cp_commit();
    load_stage(1, 1);
    cp_commit();

    for (int c = 0; c < NC; c++) {
        cp_wait<1>();
        __syncthreads();

        if (c + 2 < NC) load_stage((c + 2) % NSTAGE, c + 2);
        cp_commit();

        const uint32_t abase = sbase + (c % NSTAGE) * PAIR_BYTES;
        const uint32_t bbase = abase + STAGE_BYTES;

        // fragment prologue: kk=0 into buffer 0
#pragma unroll
        for (int mt = 0; mt < 4; mt++)
            ldsm4(af[0][mt], abase + aoff + (uint32_t)(mt * 16 * LDSK) * 4);
#pragma unroll
        for (int p = 0; p < 4; p++)
            ldsm4(&bf[0][2 * p][0], bbase + boff + (uint32_t)(p * 16 * LDSK) * 4);

#pragma unroll
        for (int kk = 0; kk < 32; kk += 8) {
            const int cur = (kk >> 3) & 1;
            const int nxt = cur ^ 1;

            // issue LDSMs for next kk-step first — latency hides under MMAs
            if (kk < 24) {
#pragma unroll
                for (int mt = 0; mt < 4; mt++)
                    ldsm4(af[nxt][mt], abase + aoff + (uint32_t)(mt * 16 * LDSK + kk + 8) * 4);
#pragma unroll
                for (int p = 0; p < 4; p++)
                    ldsm4(&bf[nxt][2 * p][0], bbase + boff + (uint32_t)(p * 16 * LDSK + kk + 8) * 4);
            }

            // MMAs on current fragments (already tf32 bits — no cvt)
#pragma unroll
            for (int mt = 0; mt < 4; mt++)
#pragma unroll
                for (int nt = 0; nt < 8; nt++)
                    mma_tf32(acc[mt][nt], af[cur][mt], bf[cur][nt]);
        }
    }

    // Epilogue
#pragma unroll
    for (int mt = 0; mt < 4; mt++) {
        const int r = m0 + wm + mt * 16 + g;
#pragma unroll
        for (int nt = 0; nt < 8; nt++) {
            const int ccol = n0 + wn + nt * 8 + tig * 2;
            float b0v = 0.f, b1v = 0.f;
            if (bias) { b0v = __ldg(bias + ccol); b1v = __ldg(bias + ccol + 1); }
            float2 v;
            v.x = acc[mt][nt][0] + b0v;
            v.y = acc[mt][nt][1] + b1v;
            *(float2*)&C[(size_t)r * N + ccol] = v;
            v.x = acc[mt][nt][2] + b0v;
            v.y = acc[mt][nt][3] + b1v;
            *(float2*)&C[(size_t)(r + 8) * N + ccol] = v;
        }
    }
}

// ---------------------------------------------------------------------------
// Attention: one block per (sequence, head). Register-blocked; writes tf32 bits.
// ---------------------------------------------------------------------------
__global__ __launch_bounds__(128) void attn_kernel(
    const float* __restrict__ qkv, uint32_t* __restrict__ o)
{
    const int nh = blockIdx.x;
    const int head = nh & (NHEADS - 1);
    const int seq = nh >> 4;
    const int w_ = seq % WW;
    const int h_ = (seq / WW) % HH;
    const int b_ = seq / (WW * HH);
    const int base = ((b_ * TT) * HH + h_) * WW + w_;

    __shared__ float Q[32][65];
    __shared__ float K[32][65];
    __shared__ float V[32][65];
    __shared__ float S[32][33];

    const int tid = threadIdx.x;

    for (int idx = tid; idx < 32 * 64; idx += 128) {
        int t = idx >> 6;
        int d = idx & 63;
        size_t off = (size_t)(base + t * TOK_TSTRIDE) * E3 + head * HDIM + d;
        Q[t][d] = qkv[off];
        K[t][d] = qkv[off + NHEADS * HDIM];
        V[t][d] = qkv[off + 2 * NHEADS * HDIM];
    }
    __syncthreads();

    const float LOG2_10000_OVER_16 = 13.287712379549449f / 16.0f;
    for (int idx = tid; idx < 32 * (ROTD / 2); idx += 128) {
        int t = idx >> 4;
        int j = idx & 15;
        float freq = exp2f(-(float)j * LOG2_10000_OVER_16);
        float ang = (float)t * freq;
        float c = cosf(ang), s = sinf(ang);
        float q0 = Q[t][2 * j], q1 = Q[t][2 * j + 1];
        Q[t][2 * j]     = q0 * c - q1 * s;
        Q[t][2 * j + 1] = q1 * c + q0 * s;
        float k0 = K[t][2 * j], k1 = K[t][2 * j + 1];
        K[t][2 * j]     = k0 * c - k1 * s;
        K[t][2 * j + 1] = k1 * c + k0 * s;
    }
    __syncthreads();

    // Scores: 2(tq) x 4(tk) per thread; skip fully-masked blocks
    {
        const int tq0 = (tid >> 3) * 2;
        const int tk0 = (tid & 7) * 4;
        if (tk0 <= tq0 + 1) {
            float s0[4] = {0.f, 0.f, 0.f, 0.f};
            float s1[4] = {0.f, 0.f, 0.f, 0.f};
#pragma unroll 8
            for (int d = 0; d < 64; d++) {
                float q0 = Q[tq0][d], q1 = Q[tq0 + 1][d];
#pragma unroll
                for (int j = 0; j < 4; j++) {
                    float kv = K[tk0 + j][d];
                    s0[j] = fmaf(q0, kv, s0[j]);
                    s1[j] = fmaf(q1, kv, s1[j]);
                }
            }
#pragma unroll
            for (int j = 0; j < 4; j++) {
                S[tq0][tk0 + j]     = s0[j] * 0.125f;
                S[tq0 + 1][tk0 + j] = s1[j] * 0.125f;
            }
        }
    }
    __syncthreads();

    if (tid < 32) {
        int row = tid;
        float m = -1e30f;
        for (int k = 0; k <= row; k++) m = fmaxf(m, S[row][k]);
        float sum = 0.f;
        for (int k = 0; k <= row; k++) {
            float e = __expf(S[row][k] - m);
            S[row][k] = e;
            sum += e;
        }
        float inv = 1.0f / sum;
        for (int k = 0; k < 32; k++)
            S[row][k] = (k <= row) ? S[row][k] * inv : 0.f;
    }
    __syncthreads();

    // O = P V: 2(t) x 8(d) per thread, causal k bound; write tf32 bits
    {
        const int t0 = (tid >> 3) * 2;
        const int d0 = (tid & 7) * 8;
        float a0[8], a1[8];
#pragma unroll
        for (int j = 0; j < 8; j++) { a0[j] = 0.f; a1[j] = 0.f; }
        const int kmax = t0 + 1;
        for (int k = 0; k <= kmax; k++) {
            float p0 = S[t0][k], p1 = S[t0 + 1][k];
#pragma unroll
            for (int j = 0; j < 8; j++) {
                float vv = V[k][d0 + j];
                a0[j] = fmaf(p0, vv, a0[j]);
                a1[j] = fmaf(p1, vv, a1[j]);
            }
        }
        uint32_t* orow0 = o + (size_t)(base + t0 * TOK_TSTRIDE) * DIMD + head * HDIM + d0;
        uint32_t* orow1 = o + (size_t)(base + (t0 + 1) * TOK_TSTRIDE) * DIMD + head * HDIM + d0;
#pragma unroll
        for (int j = 0; j < 8; j++) { orow0[j] = f2tf32(a0[j]); orow1[j] = f2tf32(a1[j]); }
    }
}

// ---------------------------------------------------------------------------
// Launch
// ---------------------------------------------------------------------------
extern "C" void kernel_launch(void* const* d_in, const int* in_sizes, int n_in,
                              void* d_out, int out_size)
{
    const float* x     = (const float*)d_in[0];   // [NTOK, 1024]
    const float* w_qkv = (const float*)d_in[1];   // [3072, 1024]
    const float* w_out = (const float*)d_in[2];   // [1024, 1024]
    const float* b_out = (const float*)d_in[3];   // [1024]
    float* out = (float*)d_out;                   // [NTOK, 1024]

    float* qkv;   uint32_t* o;
    uint32_t* xt; uint32_t* wqt; uint32_t* wot;
    cudaGetSymbolAddress((void**)&qkv, g_qkv);
    cudaGetSymbolAddress((void**)&o,   g_o);
    cudaGetSymbolAddress((void**)&xt,  g_xt);
    cudaGetSymbolAddress((void**)&wqt, g_wqt);
    cudaGetSymbolAddress((void**)&wot, g_wot);

    cudaFuncSetAttribute(gemm_tf32, cudaFuncAttributeMaxDynamicSharedMemorySize, GSMEM_BYTES);

    // 0) Convert inputs to tf32 bits (rna)
    {
        int n4 = NTOK * DIMD / 4;
        cvt_tf32<<<(n4 + 255) / 256, 256>>>((const float4*)x, (uint4*)xt, n4);
        n4 = E3 * DIMD / 4;
        cvt_tf32<<<(n4 + 255) / 256, 256>>>((const float4*)w_qkv, (uint4*)wqt, n4);
        n4 = DIMD * DIMD / 4;
        cvt_tf32<<<(n4 + 255) / 256, 256>>>((const float4*)w_out, (uint4*)wot, n4);
    }

    // 1) QKV projection
    {
        dim3 grid(E3 / 128, NTOK / 128);
        gemm_tf32<<<grid, 128, GSMEM_BYTES>>>(xt, wqt, nullptr, qkv, NTOK, E3, DIMD);
    }

    // 2) Attention (tf32-bit output)
    {
        int nblocks = (BB * HH * WW) * NHEADS;
        attn_kernel<<<nblocks, 128>>>(qkv, o);
    }

    // 3) Output projection
    {
        dim3 grid(DIMD / 128, NTOK / 128);
        gemm_tf32<<<grid, 128, GSMEM_BYTES>>>(o, wot, b_out, out, NTOK, DIMD, DIMD);
    }
}

// round 10
// speedup vs baseline: 1.0859x; 1.0215x over previous
#include <cuda_runtime.h>
#include <cuda_bf16.h>
#include <cstdint>

// Problem constants
#define DIMD 1024
#define NHEADS 16
#define HDIM 64
#define ROTD 32
#define BB 2
#define TT 32
#define HH 18
#define WW 32
#define NTOK (BB*TT*HH*WW)        // 36864
#define E3 (3*NHEADS*HDIM)        // 3072
#define TOK_TSTRIDE (HH*WW)       // 576

// Scratch (__device__ globals; allocation-free rule)
__device__ float    g_qkv[(size_t)NTOK * E3];     // fp32 qkv (attention input)
__device__ uint32_t g_o[(size_t)NTOK * DIMD];     // attention output, tf32 bits
__device__ uint32_t g_xt[(size_t)NTOK * DIMD];    // x as tf32 bits
__device__ uint32_t g_wqt[(size_t)E3 * DIMD];     // w_qkv tf32 bits
__device__ uint32_t g_wot[(size_t)DIMD * DIMD];   // w_out tf32 bits

// ---------------------------------------------------------------------------
// Helpers
// ---------------------------------------------------------------------------
__device__ __forceinline__ uint32_t smem_u32(const void* p) {
    uint32_t a;
    asm("{ .reg .u64 t; cvta.to.shared.u64 t, %1; cvt.u32.u64 %0, t; }" : "=r"(a) : "l"(p));
    return a;
}
__device__ __forceinline__ uint32_t f2tf32(float f) {
    uint32_t r;
    asm("cvt.rna.tf32.f32 %0, %1;" : "=r"(r) : "f"(f));
    return r;
}
__device__ __forceinline__ void cp16(uint32_t saddr, const void* gaddr) {
    asm volatile("cp.async.cg.shared.global [%0], [%1], 16;" :: "r"(saddr), "l"(gaddr));
}
__device__ __forceinline__ void cp_commit() {
    asm volatile("cp.async.commit_group;" ::: "memory");
}
template <int N>
__device__ __forceinline__ void cp_wait() {
    asm volatile("cp.async.wait_group %0;" :: "n"(N) : "memory");
}
__device__ __forceinline__ void ldsm4(uint32_t* r, uint32_t addr) {
    asm volatile("ldmatrix.sync.aligned.m8n8.x4.shared.b16 {%0,%1,%2,%3}, [%4];"
                 : "=r"(r[0]), "=r"(r[1]), "=r"(r[2]), "=r"(r[3]) : "r"(addr));
}
__device__ __forceinline__ void mma_tf32(float c[4],
                                         const uint32_t a[4], const uint32_t b[2]) {
    asm volatile(
        "mma.sync.aligned.m16n8k8.row.col.f32.tf32.tf32.f32 "
        "{%0,%1,%2,%3}, {%4,%5,%6,%7}, {%8,%9}, {%0,%1,%2,%3};"
        : "+f"(c[0]), "+f"(c[1]), "+f"(c[2]), "+f"(c[3])
        : "r"(a[0]), "r"(a[1]), "r"(a[2]), "r"(a[3]), "r"(b[0]), "r"(b[1]));
}

// ---------------------------------------------------------------------------
// fp32 -> tf32 bits (rna), elementwise. n in float4 units.
// ---------------------------------------------------------------------------
__global__ __launch_bounds__(256) void cvt_tf32(const float4* __restrict__ in,
                                                uint4* __restrict__ out, int n4)
{
    int i = blockIdx.x * 256 + threadIdx.x;
    if (i < n4) {
        float4 v = in[i];
        uint4 o;
        o.x = f2tf32(v.x); o.y = f2tf32(v.y); o.z = f2tf32(v.z); o.w = f2tf32(v.w);
        out[i] = o;
    }
}

// ---------------------------------------------------------------------------
// TF32 GEMM: C[M,N] = A[M,K] * B[N,K]^T (+bias). A,B hold tf32 bits.
// CTA 128x128, BK=32, 256 threads (8 warps, 2m x 4n grid, 64x32 warp tile),
// 3-stage cp.async pipeline, ldmatrix fragments, m16n8k8 tf32 mma.
// 2 CTAs/SM -> 4 warps/SMSP to fill tensor-pipe bubbles.
// ---------------------------------------------------------------------------
#define NSTAGE 3
#define LDSK 36                          // u32 row stride (32 data + 4 pad)
#define STAGE_U32 (128 * LDSK)
#define STAGE_BYTES (STAGE_U32 * 4)      // 18432
#define PAIR_BYTES (2 * STAGE_BYTES)     // 36864
#define GSMEM_BYTES (NSTAGE * PAIR_BYTES) // 110592

__global__ __launch_bounds__(256, 2) void gemm_tf32(
    const uint32_t* __restrict__ A, const uint32_t* __restrict__ B,
    const float* __restrict__ bias, float* __restrict__ C,
    int M, int N, int K)
{
    extern __shared__ uint32_t sm_[];
    const uint32_t sbase = smem_u32(sm_);

    const int tid = threadIdx.x;
    const int wid = tid >> 5;
    const int lid = tid & 31;
    const int g   = lid >> 2;
    const int tig = lid & 3;
    const int wm  = (wid >> 2) * 64;     // m: 0 or 64
    const int wn  = (wid & 3) * 32;      // n: 0,32,64,96
    const int m0 = blockIdx.y * 128;
    const int n0 = blockIdx.x * 128;

    const int K4 = K >> 2;
    const uint4* A4 = (const uint4*)A;
    const uint4* B4 = (const uint4*)B;

    // Loader mapping: f4 index i = tid + j*256 -> row = i>>3, kc4 = i&7 (j<4)
    const int lrow = tid >> 3;   // 0..31
    const int lkc4 = tid & 7;

    // Fragment lane offsets (u32 units within a stage matrix)
    const int a_lane = ((lid & 7) + ((lid >> 3) & 1) * 8) * LDSK + ((lid >> 4) & 1) * 4;
    const int b_lane = ((lid & 7) + ((lid >> 4) & 1) * 8) * LDSK + ((lid >> 3) & 1) * 4;
    const uint32_t aoff = (uint32_t)(wm * LDSK + a_lane) * 4;   // bytes
    const uint32_t boff = (uint32_t)(wn * LDSK + b_lane) * 4;

    float acc[4][4][4];                  // 4 m16-tiles x 4 n8-tiles
#pragma unroll
    for (int mt = 0; mt < 4; mt++)
#pragma unroll
        for (int nt = 0; nt < 4; nt++)
#pragma unroll
            for (int e = 0; e < 4; e++) acc[mt][nt][e] = 0.f;

    const int NC = K >> 5;

    auto load_stage = [&](int s, int c) {
        const uint32_t abase = sbase + s * PAIR_BYTES;
        const uint32_t bbase = abase + STAGE_BYTES;
        const int kb4 = c * 8;
#pragma unroll
        for (int j = 0; j < 4; j++) {
            const int row = j * 32 + lrow;
            const uint32_t soff = (uint32_t)(row * LDSK + lkc4 * 4) * 4;
            cp16(abase + soff, A4 + (size_t)(m0 + row) * K4 + kb4 + lkc4);
            cp16(bbase + soff, B4 + (size_t)(n0 + row) * K4 + kb4 + lkc4);
        }
    };

    load_stage(0, 0);
    cp_commit();
    load_stage(1, 1);
    cp_commit();

    for (int c = 0; c < NC; c++) {
        cp_wait<1>();
        __syncthreads();

        if (c + 2 < NC) load_stage((c + 2) % NSTAGE, c + 2);
        cp_commit();

        const uint32_t abase = sbase + (c % NSTAGE) * PAIR_BYTES;
        const uint32_t bbase = abase + STAGE_BYTES;

#pragma unroll
        for (int kk = 0; kk < 32; kk += 8) {
            uint32_t af[4][4];
            uint32_t bf[4][2];
#pragma unroll
            for (int mt = 0; mt < 4; mt++)
                ldsm4(af[mt], abase + aoff + (uint32_t)(mt * 16 * LDSK + kk) * 4);
#pragma unroll
            for (int p = 0; p < 2; p++)
                ldsm4(&bf[2 * p][0], bbase + boff + (uint32_t)(p * 16 * LDSK + kk) * 4);
#pragma unroll
            for (int mt = 0; mt < 4; mt++)
#pragma unroll
                for (int nt = 0; nt < 4; nt++)
                    mma_tf32(acc[mt][nt], af[mt], bf[nt]);
        }
    }

    // Epilogue
#pragma unroll
    for (int mt = 0; mt < 4; mt++) {
        const int r = m0 + wm + mt * 16 + g;
#pragma unroll
        for (int nt = 0; nt < 4; nt++) {
            const int ccol = n0 + wn + nt * 8 + tig * 2;
            float b0v = 0.f, b1v = 0.f;
            if (bias) { b0v = __ldg(bias + ccol); b1v = __ldg(bias + ccol + 1); }
            float2 v;
            v.x = acc[mt][nt][0] + b0v;
            v.y = acc[mt][nt][1] + b1v;
            *(float2*)&C[(size_t)r * N + ccol] = v;
            v.x = acc[mt][nt][2] + b0v;
            v.y = acc[mt][nt][3] + b1v;
            *(float2*)&C[(size_t)(r + 8) * N + ccol] = v;
        }
    }
}

// ---------------------------------------------------------------------------
// Attention: one block per (sequence, head). Register-blocked; writes tf32 bits.
// ---------------------------------------------------------------------------
__global__ __launch_bounds__(128) void attn_kernel(
    const float* __restrict__ qkv, uint32_t* __restrict__ o)
{
    const int nh = blockIdx.x;
    const int head = nh & (NHEADS - 1);
    const int seq = nh >> 4;
    const int w_ = seq % WW;
    const int h_ = (seq / WW) % HH;
    const int b_ = seq / (WW * HH);
    const int base = ((b_ * TT) * HH + h_) * WW + w_;

    __shared__ float Q[32][65];
    __shared__ float K[32][65];
    __shared__ float V[32][65];
    __shared__ float S[32][33];

    const int tid = threadIdx.x;

    for (int idx = tid; idx < 32 * 64; idx += 128) {
        int t = idx >> 6;
        int d = idx & 63;
        size_t off = (size_t)(base + t * TOK_TSTRIDE) * E3 + head * HDIM + d;
        Q[t][d] = qkv[off];
        K[t][d] = qkv[off + NHEADS * HDIM];
        V[t][d] = qkv[off + 2 * NHEADS * HDIM];
    }
    __syncthreads();

    const float LOG2_10000_OVER_16 = 13.287712379549449f / 16.0f;
    for (int idx = tid; idx < 32 * (ROTD / 2); idx += 128) {
        int t = idx >> 4;
        int j = idx & 15;
        float freq = exp2f(-(float)j * LOG2_10000_OVER_16);
        float ang = (float)t * freq;
        float c = cosf(ang), s = sinf(ang);
        float q0 = Q[t][2 * j], q1 = Q[t][2 * j + 1];
        Q[t][2 * j]     = q0 * c - q1 * s;
        Q[t][2 * j + 1] = q1 * c + q0 * s;
        float k0 = K[t][2 * j], k1 = K[t][2 * j + 1];
        K[t][2 * j]     = k0 * c - k1 * s;
        K[t][2 * j + 1] = k1 * c + k0 * s;
    }
    __syncthreads();

    // Scores: 2(tq) x 4(tk) per thread; skip fully-masked blocks
    {
        const int tq0 = (tid >> 3) * 2;
        const int tk0 = (tid & 7) * 4;
        if (tk0 <= tq0 + 1) {
            float s0[4] = {0.f, 0.f, 0.f, 0.f};
            float s1[4] = {0.f, 0.f, 0.f, 0.f};
#pragma unroll 8
            for (int d = 0; d < 64; d++) {
                float q0 = Q[tq0][d], q1 = Q[tq0 + 1][d];
#pragma unroll
                for (int j = 0; j < 4; j++) {
                    float kv = K[tk0 + j][d];
                    s0[j] = fmaf(q0, kv, s0[j]);
                    s1[j] = fmaf(q1, kv, s1[j]);
                }
            }
#pragma unroll
            for (int j = 0; j < 4; j++) {
                S[tq0][tk0 + j]     = s0[j] * 0.125f;
                S[tq0 + 1][tk0 + j] = s1[j] * 0.125f;
            }
        }
    }
    __syncthreads();

    if (tid < 32) {
        int row = tid;
        float m = -1e30f;
        for (int k = 0; k <= row; k++) m = fmaxf(m, S[row][k]);
        float sum = 0.f;
        for (int k = 0; k <= row; k++) {
            float e = __expf(S[row][k] - m);
            S[row][k] = e;
            sum += e;
        }
        float inv = 1.0f / sum;
        for (int k = 0; k < 32; k++)
            S[row][k] = (k <= row) ? S[row][k] * inv : 0.f;
    }
    __syncthreads();

    // O = P V: 2(t) x 8(d) per thread, causal k bound; write tf32 bits
    {
        const int t0 = (tid >> 3) * 2;
        const int d0 = (tid & 7) * 8;
        float a0[8], a1[8];
#pragma unroll
        for (int j = 0; j < 8; j++) { a0[j] = 0.f; a1[j] = 0.f; }
        const int kmax = t0 + 1;
        for (int k = 0; k <= kmax; k++) {
            float p0 = S[t0][k], p1 = S[t0 + 1][k];
#pragma unroll
            for (int j = 0; j < 8; j++) {
                float vv = V[k][d0 + j];
                a0[j] = fmaf(p0, vv, a0[j]);
                a1[j] = fmaf(p1, vv, a1[j]);
            }
        }
        uint32_t* orow0 = o + (size_t)(base + t0 * TOK_TSTRIDE) * DIMD + head * HDIM + d0;
        uint32_t* orow1 = o + (size_t)(base + (t0 + 1) * TOK_TSTRIDE) * DIMD + head * HDIM + d0;
#pragma unroll
        for (int j = 0; j < 8; j++) { orow0[j] = f2tf32(a0[j]); orow1[j] = f2tf32(a1[j]); }
    }
}

// ---------------------------------------------------------------------------
// Launch
// ---------------------------------------------------------------------------
extern "C" void kernel_launch(void* const* d_in, const int* in_sizes, int n_in,
                              void* d_out, int out_size)
{
    const float* x     = (const float*)d_in[0];   // [NTOK, 1024]
    const float* w_qkv = (const float*)d_in[1];   // [3072, 1024]
    const float* w_out = (const float*)d_in[2];   // [1024, 1024]
    const float* b_out = (const float*)d_in[3];   // [1024]
    float* out = (float*)d_out;                   // [NTOK, 1024]

    float* qkv;   uint32_t* o;
    uint32_t* xt; uint32_t* wqt; uint32_t* wot;
    cudaGetSymbolAddress((void**)&qkv, g_qkv);
    cudaGetSymbolAddress((void**)&o,   g_o);
    cudaGetSymbolAddress((void**)&xt,  g_xt);
    cudaGetSymbolAddress((void**)&wqt, g_wqt);
    cudaGetSymbolAddress((void**)&wot, g_wot);

    cudaFuncSetAttribute(gemm_tf32, cudaFuncAttributeMaxDynamicSharedMemorySize, GSMEM_BYTES);

    // 0) Convert inputs to tf32 bits (rna)
    {
        int n4 = NTOK * DIMD / 4;
        cvt_tf32<<<(n4 + 255) / 256, 256>>>((const float4*)x, (uint4*)xt, n4);
        n4 = E3 * DIMD / 4;
        cvt_tf32<<<(n4 + 255) / 256, 256>>>((const float4*)w_qkv, (uint4*)wqt, n4);
        n4 = DIMD * DIMD / 4;
        cvt_tf32<<<(n4 + 255) / 256, 256>>>((const float4*)w_out, (uint4*)wot, n4);
    }

    // 1) QKV projection
    {
        dim3 grid(E3 / 128, NTOK / 128);
        gemm_tf32<<<grid, 256, GSMEM_BYTES>>>(xt, wqt, nullptr, qkv, NTOK, E3, DIMD);
    }

    // 2) Attention (tf32-bit output)
    {
        int nblocks = (BB * HH * WW) * NHEADS;
        attn_kernel<<<nblocks, 128>>>(qkv, o);
    }

    // 3) Output projection
    {
        dim3 grid(DIMD / 128, NTOK / 128);
        gemm_tf32<<<grid, 256, GSMEM_BYTES>>>(o, wot, b_out, out, NTOK, DIMD, DIMD);
    }
}

// round 12
// speedup vs baseline: 1.7027x; 1.5680x over previous
#include <cuda_runtime.h>
#include <cuda_fp16.h>
#include <cstdint>

// Problem constants
#define DIMD 1024
#define NHEADS 16
#define HDIM 64
#define ROTD 32
#define BB 2
#define TT 32
#define HH 18
#define WW 32
#define NTOK (BB*TT*HH*WW)        // 36864
#define E3 (3*NHEADS*HDIM)        // 3072
#define TOK_TSTRIDE (HH*WW)       // 576

// Scratch (__device__ globals; allocation-free rule)
__device__ float  g_qkv[(size_t)NTOK * E3];     // fp32 qkv (attention input)
__device__ __half g_o[(size_t)NTOK * DIMD];     // attention output, fp16
__device__ __half g_xt[(size_t)NTOK * DIMD];    // x as fp16
__device__ __half g_wqt[(size_t)E3 * DIMD];     // w_qkv fp16
__device__ __half g_wot[(size_t)DIMD * DIMD];   // w_out fp16

// ---------------------------------------------------------------------------
// Helpers
// ---------------------------------------------------------------------------
__device__ __forceinline__ uint32_t smem_u32(const void* p) {
    uint32_t a;
    asm("{ .reg .u64 t; cvta.to.shared.u64 t, %1; cvt.u32.u64 %0, t; }" : "=r"(a) : "l"(p));
    return a;
}
__device__ __forceinline__ void cp16(uint32_t saddr, const void* gaddr) {
    asm volatile("cp.async.cg.shared.global [%0], [%1], 16;" :: "r"(saddr), "l"(gaddr));
}
__device__ __forceinline__ void cp_commit() {
    asm volatile("cp.async.commit_group;" ::: "memory");
}
template <int N>
__device__ __forceinline__ void cp_wait() {
    asm volatile("cp.async.wait_group %0;" :: "n"(N) : "memory");
}
__device__ __forceinline__ void ldsm4(uint32_t* r, uint32_t addr) {
    asm volatile("ldmatrix.sync.aligned.m8n8.x4.shared.b16 {%0,%1,%2,%3}, [%4];"
                 : "=r"(r[0]), "=r"(r[1]), "=r"(r[2]), "=r"(r[3]) : "r"(addr));
}
__device__ __forceinline__ void mma_f16(float c[4],
                                        const uint32_t a[4], const uint32_t b[2]) {
    asm volatile(
        "mma.sync.aligned.m16n8k16.row.col.f32.f16.f16.f32 "
        "{%0,%1,%2,%3}, {%4,%5,%6,%7}, {%8,%9}, {%0,%1,%2,%3};"
        : "+f"(c[0]), "+f"(c[1]), "+f"(c[2]), "+f"(c[3])
        : "r"(a[0]), "r"(a[1]), "r"(a[2]), "r"(a[3]), "r"(b[0]), "r"(b[1]));
}

// ---------------------------------------------------------------------------
// fp32 -> fp16 (rn) elementwise. n in float4 units.
// ---------------------------------------------------------------------------
__global__ __launch_bounds__(256) void cvt_f16(const float4* __restrict__ in,
                                               uint2* __restrict__ out, int n4)
{
    int i = blockIdx.x * 256 + threadIdx.x;
    if (i < n4) {
        float4 v = in[i];
        __half2 h0 = __floats2half2_rn(v.x, v.y);
        __half2 h1 = __floats2half2_rn(v.z, v.w);
        uint2 o;
        o.x = *reinterpret_cast<uint32_t*>(&h0);
        o.y = *reinterpret_cast<uint32_t*>(&h1);
        out[i] = o;
    }
}

// ---------------------------------------------------------------------------
// FP16 GEMM (fp32 accum): C[M,N] = A[M,K] * B[N,K]^T (+bias). A,B fp16.
// CTA 128x128, BK=32, 256 threads (8 warps, 2m x 4n, 64x32 warp tile),
// 3-stage cp.async pipeline, ldmatrix, m16n8k16.
// SMEM rows: 32 halves data + 8 pad = 40 halves (80 B) -> conflict-free
// ldmatrix phases (banks 20r mod 32 all distinct).
// ---------------------------------------------------------------------------
#define NSTAGE 3
#define SKH 40                             // halves per row stride
#define ROWB (SKH * 2)                     // 80 bytes
#define STAGE_BYTES (128 * ROWB)           // 10240
#define PAIR_BYTES (2 * STAGE_BYTES)       // 20480
#define GSMEM_BYTES (NSTAGE * PAIR_BYTES)  // 61440

__global__ __launch_bounds__(256, 2) void gemm_f16(
    const __half* __restrict__ A, const __half* __restrict__ B,
    const float* __restrict__ bias, float* __restrict__ C,
    int M, int N, int K)
{
    extern __shared__ uint32_t sm_[];
    const uint32_t sbase = smem_u32(sm_);

    const int tid = threadIdx.x;
    const int wid = tid >> 5;
    const int lid = tid & 31;
    const int g   = lid >> 2;
    const int tig = lid & 3;
    const int wm  = (wid >> 2) * 64;     // m: 0 or 64
    const int wn  = (wid & 3) * 32;      // n: 0,32,64,96
    const int m0 = blockIdx.y * 128;
    const int n0 = blockIdx.x * 128;

    // Loader: 512 16B-chunks per matrix per stage (128 rows x 4 chunks).
    // i = tid + j*256 (j<2): row = i>>2, c16 = i&3.
    const int lrow = tid >> 2;           // 0..63 (j adds 64)
    const int lc16 = tid & 3;

    // Fragment lane byte-offsets within a stage matrix.
    // A: lanes 0-15 -> rows 0-15 (k bytes +0), lanes 16-31 -> rows 0-15 (+16B)
    const uint32_t aoff = (uint32_t)((wm + (lid & 15)) * ROWB + (lid >> 4) * 16);
    // B: lanes 0-7 n-rows 0-7 k0; 8-15 n0-7 +16B; 16-23 n8-15 k0; 24-31 n8-15 +16B
    const uint32_t boff = (uint32_t)((wn + (lid & 7) + ((lid >> 4) & 1) * 8) * ROWB
                                     + ((lid >> 3) & 1) * 16);

    float acc[4][4][4];
#pragma unroll
    for (int mt = 0; mt < 4; mt++)
#pragma unroll
        for (int nt = 0; nt < 4; nt++)
#pragma unroll
            for (int e = 0; e < 4; e++) acc[mt][nt][e] = 0.f;

    const int NC = K >> 5;   // K/32

    auto load_stage = [&](int s, int c) {
        const uint32_t abase = sbase + s * PAIR_BYTES;
        const uint32_t bbase = abase + STAGE_BYTES;
        const int kb = c * 32;           // half offset along K
#pragma unroll
        for (int j = 0; j < 2; j++) {
            const int row = j * 64 + lrow;
            const uint32_t soff = (uint32_t)(row * ROWB + lc16 * 16);
            cp16(abase + soff, A + (size_t)(m0 + row) * K + kb + lc16 * 8);
            cp16(bbase + soff, B + (size_t)(n0 + row) * K + kb + lc16 * 8);
        }
    };

    load_stage(0, 0);
    cp_commit();
    load_stage(1, 1);
    cp_commit();

    for (int c = 0; c < NC; c++) {
        cp_wait<1>();
        __syncthreads();

        if (c + 2 < NC) load_stage((c + 2) % NSTAGE, c + 2);
        cp_commit();

        const uint32_t abase = sbase + (c % NSTAGE) * PAIR_BYTES;
        const uint32_t bbase = abase + STAGE_BYTES;

#pragma unroll
        for (int kk = 0; kk < 32; kk += 16) {
            uint32_t af[4][4];
            uint32_t bf[4][2];
#pragma unroll
            for (int mt = 0; mt < 4; mt++)
                ldsm4(af[mt], abase + aoff + (uint32_t)(mt * 16 * ROWB + kk * 2));
#pragma unroll
            for (int p = 0; p < 2; p++)
                ldsm4(&bf[2 * p][0], bbase + boff + (uint32_t)(p * 16 * ROWB + kk * 2));
#pragma unroll
            for (int mt = 0; mt < 4; mt++)
#pragma unroll
                for (int nt = 0; nt < 4; nt++)
                    mma_f16(acc[mt][nt], af[mt], bf[nt]);
        }
    }

    // Epilogue
#pragma unroll
    for (int mt = 0; mt < 4; mt++) {
        const int r = m0 + wm + mt * 16 + g;
#pragma unroll
        for (int nt = 0; nt < 4; nt++) {
            const int ccol = n0 + wn + nt * 8 + tig * 2;
            float b0v = 0.f, b1v = 0.f;
            if (bias) { b0v = __ldg(bias + ccol); b1v = __ldg(bias + ccol + 1); }
            float2 v;
            v.x = acc[mt][nt][0] + b0v;
            v.y = acc[mt][nt][1] + b1v;
            *(float2*)&C[(size_t)r * N + ccol] = v;
            v.x = acc[mt][nt][2] + b0v;
            v.y = acc[mt][nt][3] + b1v;
            *(float2*)&C[(size_t)(r + 8) * N + ccol] = v;
        }
    }
}

// ---------------------------------------------------------------------------
// Attention: one block per (sequence, head). Register-blocked; writes fp16.
// ---------------------------------------------------------------------------
__global__ __launch_bounds__(128) void attn_kernel(
    const float* __restrict__ qkv, __half* __restrict__ o)
{
    const int nh = blockIdx.x;
    const int head = nh & (NHEADS - 1);
    const int seq = nh >> 4;
    const int w_ = seq % WW;
    const int h_ = (seq / WW) % HH;
    const int b_ = seq / (WW * HH);
    const int base = ((b_ * TT) * HH + h_) * WW + w_;

    __shared__ float Q[32][65];
    __shared__ float K[32][65];
    __shared__ float V[32][65];
    __shared__ float S[32][33];

    const int tid = threadIdx.x;

    for (int idx = tid; idx < 32 * 64; idx += 128) {
        int t = idx >> 6;
        int d = idx & 63;
        size_t off = (size_t)(base + t * TOK_TSTRIDE) * E3 + head * HDIM + d;
        Q[t][d] = qkv[off];
        K[t][d] = qkv[off + NHEADS * HDIM];
        V[t][d] = qkv[off + 2 * NHEADS * HDIM];
    }
    __syncthreads();

    const float LOG2_10000_OVER_16 = 13.287712379549449f / 16.0f;
    for (int idx = tid; idx < 32 * (ROTD / 2); idx += 128) {
        int t = idx >> 4;
        int j = idx & 15;
        float freq = exp2f(-(float)j * LOG2_10000_OVER_16);
        float ang = (float)t * freq;
        float c = cosf(ang), s = sinf(ang);
        float q0 = Q[t][2 * j], q1 = Q[t][2 * j + 1];
        Q[t][2 * j]     = q0 * c - q1 * s;
        Q[t][2 * j + 1] = q1 * c + q0 * s;
        float k0 = K[t][2 * j], k1 = K[t][2 * j + 1];
        K[t][2 * j]     = k0 * c - k1 * s;
        K[t][2 * j + 1] = k1 * c + k0 * s;
    }
    __syncthreads();

    // Scores: 2(tq) x 4(tk) per thread; skip fully-masked blocks
    {
        const int tq0 = (tid >> 3) * 2;
        const int tk0 = (tid & 7) * 4;
        if (tk0 <= tq0 + 1) {
            float s0[4] = {0.f, 0.f, 0.f, 0.f};
            float s1[4] = {0.f, 0.f, 0.f, 0.f};
#pragma unroll 8
            for (int d = 0; d < 64; d++) {
                float q0 = Q[tq0][d], q1 = Q[tq0 + 1][d];
#pragma unroll
                for (int j = 0; j < 4; j++) {
                    float kv = K[tk0 + j][d];
                    s0[j] = fmaf(q0, kv, s0[j]);
                    s1[j] = fmaf(q1, kv, s1[j]);
                }
            }
#pragma unroll
            for (int j = 0; j < 4; j++) {
                S[tq0][tk0 + j]     = s0[j] * 0.125f;
                S[tq0 + 1][tk0 + j] = s1[j] * 0.125f;
            }
        }
    }
    __syncthreads();

    if (tid < 32) {
        int row = tid;
        float m = -1e30f;
        for (int k = 0; k <= row; k++) m = fmaxf(m, S[row][k]);
        float sum = 0.f;
        for (int k = 0; k <= row; k++) {
            float e = __expf(S[row][k] - m);
            S[row][k] = e;
            sum += e;
        }
        float inv = 1.0f / sum;
        for (int k = 0; k < 32; k++)
            S[row][k] = (k <= row) ? S[row][k] * inv : 0.f;
    }
    __syncthreads();

    // O = P V: 2(t) x 8(d) per thread, causal k bound; write fp16
    {
        const int t0 = (tid >> 3) * 2;
        const int d0 = (tid & 7) * 8;
        float a0[8], a1[8];
#pragma unroll
        for (int j = 0; j < 8; j++) { a0[j] = 0.f; a1[j] = 0.f; }
        const int kmax = t0 + 1;
        for (int k = 0; k <= kmax; k++) {
            float p0 = S[t0][k], p1 = S[t0 + 1][k];
#pragma unroll
            for (int j = 0; j < 8; j++) {
                float vv = V[k][d0 + j];
                a0[j] = fmaf(p0, vv, a0[j]);
                a1[j] = fmaf(p1, vv, a1[j]);
            }
        }
        __half* orow0 = o + (size_t)(base + t0 * TOK_TSTRIDE) * DIMD + head * HDIM + d0;
        __half* orow1 = o + (size_t)(base + (t0 + 1) * TOK_TSTRIDE) * DIMD + head * HDIM + d0;
#pragma unroll
        for (int j = 0; j < 8; j++) {
            orow0[j] = __float2half_rn(a0[j]);
            orow1[j] = __float2half_rn(a1[j]);
        }
    }
}

// ---------------------------------------------------------------------------
// Launch
// ---------------------------------------------------------------------------
extern "C" void kernel_launch(void* const* d_in, const int* in_sizes, int n_in,
                              void* d_out, int out_size)
{
    const float* x     = (const float*)d_in[0];   // [NTOK, 1024]
    const float* w_qkv = (const float*)d_in[1];   // [3072, 1024]
    const float* w_out = (const float*)d_in[2];   // [1024, 1024]
    const float* b_out = (const float*)d_in[3];   // [1024]
    float* out = (float*)d_out;                   // [NTOK, 1024]

    float* qkv; __half* o;
    __half* xt; __half* wqt; __half* wot;
    cudaGetSymbolAddress((void**)&qkv, g_qkv);
    cudaGetSymbolAddress((void**)&o,   g_o);
    cudaGetSymbolAddress((void**)&xt,  g_xt);
    cudaGetSymbolAddress((void**)&wqt, g_wqt);
    cudaGetSymbolAddress((void**)&wot, g_wot);

    cudaFuncSetAttribute(gemm_f16, cudaFuncAttributeMaxDynamicSharedMemorySize, GSMEM_BYTES);

    // 0) Convert inputs to fp16 (rn)
    {
        int n4 = NTOK * DIMD / 4;
        cvt_f16<<<(n4 + 255) / 256, 256>>>((const float4*)x, (uint2*)xt, n4);
        n4 = E3 * DIMD / 4;
        cvt_f16<<<(n4 + 255) / 256, 256>>>((const float4*)w_qkv, (uint2*)wqt, n4);
        n4 = DIMD * DIMD / 4;
        cvt_f16<<<(n4 + 255) / 256, 256>>>((const float4*)w_out, (uint2*)wot, n4);
    }

    // 1) QKV projection: [36864,1024] x [3072,1024]^T -> [36864,3072]
    {
        dim3 grid(E3 / 128, NTOK / 128);
        gemm_f16<<<grid, 256, GSMEM_BYTES>>>(xt, wqt, nullptr, qkv, NTOK, E3, DIMD);
    }

    // 2) Attention (fp16 output)
    {
        int nblocks = (BB * HH * WW) * NHEADS;
        attn_kernel<<<nblocks, 128>>>(qkv, o);
    }

    // 3) Output projection: [36864,1024] x [1024,1024]^T + bias
    {
        dim3 grid(DIMD / 128, NTOK / 128);
        gemm_f16<<<grid, 256, GSMEM_BYTES>>>(o, wot, b_out, out, NTOK, DIMD, DIMD);
    }
}

// round 14
// speedup vs baseline: 1.7965x; 1.0551x over previous
#include <cuda_runtime.h>
#include <cuda_fp16.h>
#include <cstdint>

// Problem constants
#define DIMD 1024
#define NHEADS 16
#define HDIM 64
#define ROTD 32
#define BB 2
#define TT 32
#define HH 18
#define WW 32
#define NTOK (BB*TT*HH*WW)        // 36864
#define E3 (3*NHEADS*HDIM)        // 3072
#define TOK_TSTRIDE (HH*WW)       // 576

// Scratch (__device__ globals; allocation-free rule)
__device__ __half g_qkv[(size_t)NTOK * E3];     // fp16 qkv (GEMM1 out, attn in)
__device__ __half g_o[(size_t)NTOK * DIMD];     // attention output, fp16
__device__ __half g_xt[(size_t)NTOK * DIMD];    // x as fp16
__device__ __half g_wqt[(size_t)E3 * DIMD];     // w_qkv fp16
__device__ __half g_wot[(size_t)DIMD * DIMD];   // w_out fp16

// ---------------------------------------------------------------------------
// Helpers
// ---------------------------------------------------------------------------
__device__ __forceinline__ uint32_t smem_u32(const void* p) {
    uint32_t a;
    asm("{ .reg .u64 t; cvta.to.shared.u64 t, %1; cvt.u32.u64 %0, t; }" : "=r"(a) : "l"(p));
    return a;
}
__device__ __forceinline__ void cp16(uint32_t saddr, const void* gaddr) {
    asm volatile("cp.async.cg.shared.global [%0], [%1], 16;" :: "r"(saddr), "l"(gaddr));
}
__device__ __forceinline__ void cp_commit() {
    asm volatile("cp.async.commit_group;" ::: "memory");
}
template <int N>
__device__ __forceinline__ void cp_wait() {
    asm volatile("cp.async.wait_group %0;" :: "n"(N) : "memory");
}
__device__ __forceinline__ void ldsm4(uint32_t* r, uint32_t addr) {
    asm volatile("ldmatrix.sync.aligned.m8n8.x4.shared.b16 {%0,%1,%2,%3}, [%4];"
                 : "=r"(r[0]), "=r"(r[1]), "=r"(r[2]), "=r"(r[3]) : "r"(addr));
}
__device__ __forceinline__ void mma_f16(float c[4],
                                        const uint32_t a[4], const uint32_t b[2]) {
    asm volatile(
        "mma.sync.aligned.m16n8k16.row.col.f32.f16.f16.f32 "
        "{%0,%1,%2,%3}, {%4,%5,%6,%7}, {%8,%9}, {%0,%1,%2,%3};"
        : "+f"(c[0]), "+f"(c[1]), "+f"(c[2]), "+f"(c[3])
        : "r"(a[0]), "r"(a[1]), "r"(a[2]), "r"(a[3]), "r"(b[0]), "r"(b[1]));
}

// ---------------------------------------------------------------------------
// fp32 -> fp16 (rn) elementwise. n in float4 units.
// ---------------------------------------------------------------------------
__global__ __launch_bounds__(256) void cvt_f16(const float4* __restrict__ in,
                                               uint2* __restrict__ out, int n4)
{
    int i = blockIdx.x * 256 + threadIdx.x;
    if (i < n4) {
        float4 v = in[i];
        __half2 h0 = __floats2half2_rn(v.x, v.y);
        __half2 h1 = __floats2half2_rn(v.z, v.w);
        uint2 o;
        o.x = *reinterpret_cast<uint32_t*>(&h0);
        o.y = *reinterpret_cast<uint32_t*>(&h1);
        out[i] = o;
    }
}

// ---------------------------------------------------------------------------
// FP16 GEMM (fp32 accum): C[M,N] = A[M,K] * B[N,K]^T (+bias). A,B fp16.
// CTA 128x128, BK=32, 128 threads (4 warps, 2m x 2n, 64x64 warp tile),
// 3-stage cp.async pipeline, ldmatrix, m16n8k16. Output type templated.
// SMEM rows: 32 halves + 8 pad = 40 halves (80 B): ldmatrix phase banks
// 20r mod 32 all distinct -> conflict-free.
// ---------------------------------------------------------------------------
#define NSTAGE 3
#define SKH 40
#define ROWB (SKH * 2)                     // 80 bytes
#define STAGE_BYTES (128 * ROWB)           // 10240
#define PAIR_BYTES (2 * STAGE_BYTES)       // 20480
#define GSMEM_BYTES (NSTAGE * PAIR_BYTES)  // 61440

template <typename OutT>
__global__ __launch_bounds__(128, 2) void gemm_f16(
    const __half* __restrict__ A, const __half* __restrict__ B,
    const float* __restrict__ bias, OutT* __restrict__ C,
    int M, int N, int K)
{
    extern __shared__ uint32_t sm_[];
    const uint32_t sbase = smem_u32(sm_);

    const int tid = threadIdx.x;
    const int wid = tid >> 5;
    const int lid = tid & 31;
    const int g   = lid >> 2;
    const int tig = lid & 3;
    const int wm  = (wid >> 1) * 64;     // m: 0 or 64
    const int wn  = (wid & 1) * 64;      // n: 0 or 64
    const int m0 = blockIdx.y * 128;
    const int n0 = blockIdx.x * 128;

    // Loader: 512 16B-chunks per matrix per stage; 128 threads x 4 iters.
    const int lrow = tid >> 2;           // 0..31 (+ j*32)
    const int lc16 = tid & 3;

    // Fragment lane byte-offsets within a stage matrix.
    const uint32_t aoff = (uint32_t)((wm + (lid & 15)) * ROWB + (lid >> 4) * 16);
    const uint32_t boff = (uint32_t)((wn + (lid & 7) + ((lid >> 4) & 1) * 8) * ROWB
                                     + ((lid >> 3) & 1) * 16);

    float acc[4][8][4];
#pragma unroll
    for (int mt = 0; mt < 4; mt++)
#pragma unroll
        for (int nt = 0; nt < 8; nt++)
#pragma unroll
            for (int e = 0; e < 4; e++) acc[mt][nt][e] = 0.f;

    const int NC = K >> 5;   // K/32

    auto load_stage = [&](int s, int c) {
        const uint32_t abase = sbase + s * PAIR_BYTES;
        const uint32_t bbase = abase + STAGE_BYTES;
        const int kb = c * 32;
#pragma unroll
        for (int j = 0; j < 4; j++) {
            const int row = j * 32 + lrow;
            const uint32_t soff = (uint32_t)(row * ROWB + lc16 * 16);
            cp16(abase + soff, A + (size_t)(m0 + row) * K + kb + lc16 * 8);
            cp16(bbase + soff, B + (size_t)(n0 + row) * K + kb + lc16 * 8);
        }
    };

    load_stage(0, 0);
    cp_commit();
    load_stage(1, 1);
    cp_commit();

    for (int c = 0; c < NC; c++) {
        cp_wait<1>();
        __syncthreads();

        if (c + 2 < NC) load_stage((c + 2) % NSTAGE, c + 2);
        cp_commit();

        const uint32_t abase = sbase + (c % NSTAGE) * PAIR_BYTES;
        const uint32_t bbase = abase + STAGE_BYTES;

#pragma unroll
        for (int kk = 0; kk < 32; kk += 16) {
            uint32_t af[4][4];
            uint32_t bf[8][2];
#pragma unroll
            for (int mt = 0; mt < 4; mt++)
                ldsm4(af[mt], abase + aoff + (uint32_t)(mt * 16 * ROWB + kk * 2));
#pragma unroll
            for (int p = 0; p < 4; p++)
                ldsm4(&bf[2 * p][0], bbase + boff + (uint32_t)(p * 16 * ROWB + kk * 2));
#pragma unroll
            for (int mt = 0; mt < 4; mt++)
#pragma unroll
                for (int nt = 0; nt < 8; nt++)
                    mma_f16(acc[mt][nt], af[mt], bf[nt]);
        }
    }

    // Epilogue
#pragma unroll
    for (int mt = 0; mt < 4; mt++) {
        const int r = m0 + wm + mt * 16 + g;
#pragma unroll
        for (int nt = 0; nt < 8; nt++) {
            const int ccol = n0 + wn + nt * 8 + tig * 2;
            float b0v = 0.f, b1v = 0.f;
            if (bias) { b0v = __ldg(bias + ccol); b1v = __ldg(bias + ccol + 1); }
            float v0 = acc[mt][nt][0] + b0v;
            float v1 = acc[mt][nt][1] + b1v;
            float v2 = acc[mt][nt][2] + b0v;
            float v3 = acc[mt][nt][3] + b1v;
            if constexpr (sizeof(OutT) == 2) {
                __half2 h01 = __floats2half2_rn(v0, v1);
                __half2 h23 = __floats2half2_rn(v2, v3);
                *(__half2*)((__half*)C + (size_t)r * N + ccol) = h01;
                *(__half2*)((__half*)C + (size_t)(r + 8) * N + ccol) = h23;
            } else {
                *(float2*)((float*)C + (size_t)r * N + ccol) = make_float2(v0, v1);
                *(float2*)((float*)C + (size_t)(r + 8) * N + ccol) = make_float2(v2, v3);
            }
        }
    }
}

// ---------------------------------------------------------------------------
// Attention: one block per (sequence, head). fp16 in/out, fp32 math.
// ---------------------------------------------------------------------------
__global__ __launch_bounds__(128) void attn_kernel(
    const __half* __restrict__ qkv, __half* __restrict__ o)
{
    const int nh = blockIdx.x;
    const int head = nh & (NHEADS - 1);
    const int seq = nh >> 4;
    const int w_ = seq % WW;
    const int h_ = (seq / WW) % HH;
    const int b_ = seq / (WW * HH);
    const int base = ((b_ * TT) * HH + h_) * WW + w_;

    __shared__ float Q[32][65];
    __shared__ float K[32][65];
    __shared__ float V[32][65];
    __shared__ float S[32][33];

    const int tid = threadIdx.x;

    // Load Q/K/V (fp16 -> fp32), vectorized by 2
    for (int idx = tid; idx < 32 * 32; idx += 128) {
        int t = idx >> 5;
        int d2 = idx & 31;               // half2 index along 64 dims
        size_t off2 = ((size_t)(base + t * TOK_TSTRIDE) * E3 + head * HDIM) / 2 + d2;
        const __half2* q2 = (const __half2*)qkv;
        float2 qv = __half22float2(q2[off2]);
        float2 kv = __half22float2(q2[off2 + NHEADS * HDIM / 2]);
        float2 vv = __half22float2(q2[off2 + NHEADS * HDIM]);
        Q[t][d2 * 2] = qv.x; Q[t][d2 * 2 + 1] = qv.y;
        K[t][d2 * 2] = kv.x; K[t][d2 * 2 + 1] = kv.y;
        V[t][d2 * 2] = vv.x; V[t][d2 * 2 + 1] = vv.y;
    }
    __syncthreads();

    const float LOG2_10000_OVER_16 = 13.287712379549449f / 16.0f;
    for (int idx = tid; idx < 32 * (ROTD / 2); idx += 128) {
        int t = idx >> 4;
        int j = idx & 15;
        float freq = exp2f(-(float)j * LOG2_10000_OVER_16);
        float ang = (float)t * freq;
        float c = cosf(ang), s = sinf(ang);
        float q0 = Q[t][2 * j], q1 = Q[t][2 * j + 1];
        Q[t][2 * j]     = q0 * c - q1 * s;
        Q[t][2 * j + 1] = q1 * c + q0 * s;
        float k0 = K[t][2 * j], k1 = K[t][2 * j + 1];
        K[t][2 * j]     = k0 * c - k1 * s;
        K[t][2 * j + 1] = k1 * c + k0 * s;
    }
    __syncthreads();

    // Scores: 2(tq) x 4(tk) per thread; skip fully-masked blocks
    {
        const int tq0 = (tid >> 3) * 2;
        const int tk0 = (tid & 7) * 4;
        if (tk0 <= tq0 + 1) {
            float s0[4] = {0.f, 0.f, 0.f, 0.f};
            float s1[4] = {0.f, 0.f, 0.f, 0.f};
#pragma unroll 8
            for (int d = 0; d < 64; d++) {
                float q0 = Q[tq0][d], q1 = Q[tq0 + 1][d];
#pragma unroll
                for (int j = 0; j < 4; j++) {
                    float kv = K[tk0 + j][d];
                    s0[j] = fmaf(q0, kv, s0[j]);
                    s1[j] = fmaf(q1, kv, s1[j]);
                }
            }
#pragma unroll
            for (int j = 0; j < 4; j++) {
                S[tq0][tk0 + j]     = s0[j] * 0.125f;
                S[tq0 + 1][tk0 + j] = s1[j] * 0.125f;
            }
        }
    }
    __syncthreads();

    if (tid < 32) {
        int row = tid;
        float m = -1e30f;
        for (int k = 0; k <= row; k++) m = fmaxf(m, S[row][k]);
        float sum = 0.f;
        for (int k = 0; k <= row; k++) {
            float e = __expf(S[row][k] - m);
            S[row][k] = e;
            sum += e;
        }
        float inv = 1.0f / sum;
        for (int k = 0; k < 32; k++)
            S[row][k] = (k <= row) ? S[row][k] * inv : 0.f;
    }
    __syncthreads();

    // O = P V: 2(t) x 8(d) per thread, causal k bound; write fp16
    {
        const int t0 = (tid >> 3) * 2;
        const int d0 = (tid & 7) * 8;
        float a0[8], a1[8];
#pragma unroll
        for (int j = 0; j < 8; j++) { a0[j] = 0.f; a1[j] = 0.f; }
        const int kmax = t0 + 1;
        for (int k = 0; k <= kmax; k++) {
            float p0 = S[t0][k], p1 = S[t0 + 1][k];
#pragma unroll
            for (int j = 0; j < 8; j++) {
                float vv = V[k][d0 + j];
                a0[j] = fmaf(p0, vv, a0[j]);
                a1[j] = fmaf(p1, vv, a1[j]);
            }
        }
        __half* orow0 = o + (size_t)(base + t0 * TOK_TSTRIDE) * DIMD + head * HDIM + d0;
        __half* orow1 = o + (size_t)(base + (t0 + 1) * TOK_TSTRIDE) * DIMD + head * HDIM + d0;
#pragma unroll
        for (int j = 0; j < 4; j++) {
            ((__half2*)orow0)[j] = __floats2half2_rn(a0[2 * j], a0[2 * j + 1]);
            ((__half2*)orow1)[j] = __floats2half2_rn(a1[2 * j], a1[2 * j + 1]);
        }
    }
}

// ---------------------------------------------------------------------------
// Launch
// ---------------------------------------------------------------------------
extern "C" void kernel_launch(void* const* d_in, const int* in_sizes, int n_in,
                              void* d_out, int out_size)
{
    const float* x     = (const float*)d_in[0];   // [NTOK, 1024]
    const float* w_qkv = (const float*)d_in[1];   // [3072, 1024]
    const float* w_out = (const float*)d_in[2];   // [1024, 1024]
    const float* b_out = (const float*)d_in[3];   // [1024]
    float* out = (float*)d_out;                   // [NTOK, 1024]

    __half* qkv; __half* o;
    __half* xt; __half* wqt; __half* wot;
    cudaGetSymbolAddress((void**)&qkv, g_qkv);
    cudaGetSymbolAddress((void**)&o,   g_o);
    cudaGetSymbolAddress((void**)&xt,  g_xt);
    cudaGetSymbolAddress((void**)&wqt, g_wqt);
    cudaGetSymbolAddress((void**)&wot, g_wot);

    cudaFuncSetAttribute(gemm_f16<__half>, cudaFuncAttributeMaxDynamicSharedMemorySize, GSMEM_BYTES);
    cudaFuncSetAttribute(gemm_f16<float>,  cudaFuncAttributeMaxDynamicSharedMemorySize, GSMEM_BYTES);

    // 0) Convert inputs to fp16 (rn)
    {
        int n4 = NTOK * DIMD / 4;
        cvt_f16<<<(n4 + 255) / 256, 256>>>((const float4*)x, (uint2*)xt, n4);
        n4 = E3 * DIMD / 4;
        cvt_f16<<<(n4 + 255) / 256, 256>>>((const float4*)w_qkv, (uint2*)wqt, n4);
        n4 = DIMD * DIMD / 4;
        cvt_f16<<<(n4 + 255) / 256, 256>>>((const float4*)w_out, (uint2*)wot, n4);
    }

    // 1) QKV projection -> fp16 qkv
    {
        dim3 grid(E3 / 128, NTOK / 128);
        gemm_f16<__half><<<grid, 128, GSMEM_BYTES>>>(xt, wqt, nullptr, qkv, NTOK, E3, DIMD);
    }

    // 2) Attention (fp16 in/out)
    {
        int nblocks = (BB * HH * WW) * NHEADS;
        attn_kernel<<<nblocks, 128>>>(qkv, o);
    }

    // 3) Output projection -> fp32 out (+bias)
    {
        dim3 grid(DIMD / 128, NTOK / 128);
        gemm_f16<float><<<grid, 128, GSMEM_BYTES>>>(o, wot, b_out, out, NTOK, DIMD, DIMD);
    }
}

// round 15
// speedup vs baseline: 1.8093x; 1.0071x over previous
#include <cuda_runtime.h>
#include <cuda_fp16.h>
#include <cstdint>

// Problem constants
#define DIMD 1024
#define NHEADS 16
#define HDIM 64
#define ROTD 32
#define BB 2
#define TT 32
#define HH 18
#define WW 32
#define NTOK (BB*TT*HH*WW)        // 36864
#define E3 (3*NHEADS*HDIM)        // 3072
#define TOK_TSTRIDE (HH*WW)       // 576

// Scratch (__device__ globals; allocation-free rule)
__device__ __half g_qkv[(size_t)NTOK * E3];     // fp16 qkv
__device__ __half g_o[(size_t)NTOK * DIMD];     // attention output fp16
__device__ __half g_xt[(size_t)NTOK * DIMD];    // x fp16
__device__ __half g_wqt[(size_t)E3 * DIMD];     // w_qkv fp16
__device__ __half g_wot[(size_t)DIMD * DIMD];   // w_out fp16

// ---------------------------------------------------------------------------
// Helpers
// ---------------------------------------------------------------------------
__device__ __forceinline__ uint32_t smem_u32(const void* p) {
    uint32_t a;
    asm("{ .reg .u64 t; cvta.to.shared.u64 t, %1; cvt.u32.u64 %0, t; }" : "=r"(a) : "l"(p));
    return a;
}
__device__ __forceinline__ void cp16(uint32_t saddr, const void* gaddr) {
    asm volatile("cp.async.cg.shared.global [%0], [%1], 16;" :: "r"(saddr), "l"(gaddr));
}
__device__ __forceinline__ void cp_commit() {
    asm volatile("cp.async.commit_group;" ::: "memory");
}
template <int N>
__device__ __forceinline__ void cp_wait() {
    asm volatile("cp.async.wait_group %0;" :: "n"(N) : "memory");
}
__device__ __forceinline__ void ldsm4(uint32_t* r, uint32_t addr) {
    asm volatile("ldmatrix.sync.aligned.m8n8.x4.shared.b16 {%0,%1,%2,%3}, [%4];"
                 : "=r"(r[0]), "=r"(r[1]), "=r"(r[2]), "=r"(r[3]) : "r"(addr));
}
__device__ __forceinline__ void mma_f16(float c[4],
                                        const uint32_t a[4], const uint32_t b[2]) {
    asm volatile(
        "mma.sync.aligned.m16n8k16.row.col.f32.f16.f16.f32 "
        "{%0,%1,%2,%3}, {%4,%5,%6,%7}, {%8,%9}, {%0,%1,%2,%3};"
        : "+f"(c[0]), "+f"(c[1]), "+f"(c[2]), "+f"(c[3])
        : "r"(a[0]), "r"(a[1]), "r"(a[2]), "r"(a[3]), "r"(b[0]), "r"(b[1]));
}

// ---------------------------------------------------------------------------
// fp32 -> fp16 (rn) elementwise. n in float4 units.
// ---------------------------------------------------------------------------
__global__ __launch_bounds__(256) void cvt_f16(const float4* __restrict__ in,
                                               uint2* __restrict__ out, int n4)
{
    int i = blockIdx.x * 256 + threadIdx.x;
    if (i < n4) {
        float4 v = in[i];
        __half2 h0 = __floats2half2_rn(v.x, v.y);
        __half2 h1 = __floats2half2_rn(v.z, v.w);
        uint2 o;
        o.x = *reinterpret_cast<uint32_t*>(&h0);
        o.y = *reinterpret_cast<uint32_t*>(&h1);
        out[i] = o;
    }
}

// ---------------------------------------------------------------------------
// FP16 GEMM (fp32 accum): C[M,N] = A[M,K] * B[N,K]^T (+bias). A,B fp16.
// CTA 128x128, BK=64 (halves per-iteration overhead vs BK=32),
// 128 threads (4 warps, 2m x 2n, 64x64 warp tile),
// 3-stage cp.async pipeline, ldmatrix, m16n8k16. Output type templated.
// SMEM rows: 64 halves data + 8 pad = 72 halves (144 B) -> ldmatrix phase
// banks 4*(9r+c) mod 32, 8 consecutive rows distinct -> conflict-free.
// ---------------------------------------------------------------------------
#define NSTAGE 3
#define BKH 64                             // K halves per iteration
#define SKH 72                             // halves per row stride
#define ROWB (SKH * 2)                     // 144 bytes
#define STAGE_BYTES (128 * ROWB)           // 18432 per matrix
#define PAIR_BYTES (2 * STAGE_BYTES)       // 36864
#define GSMEM_BYTES (NSTAGE * PAIR_BYTES)  // 110592

template <typename OutT>
__global__ __launch_bounds__(128, 2) void gemm_f16(
    const __half* __restrict__ A, const __half* __restrict__ B,
    const float* __restrict__ bias, OutT* __restrict__ C,
    int M, int N, int K)
{
    extern __shared__ uint32_t sm_[];
    const uint32_t sbase = smem_u32(sm_);

    const int tid = threadIdx.x;
    const int wid = tid >> 5;
    const int lid = tid & 31;
    const int g   = lid >> 2;
    const int tig = lid & 3;
    const int wm  = (wid >> 1) * 64;     // m: 0 or 64
    const int wn  = (wid & 1) * 64;      // n: 0 or 64
    const int m0 = blockIdx.y * 128;
    const int n0 = blockIdx.x * 128;

    // Loader: per matrix per stage = 128 rows x 8 chunks(16B) = 1024 chunks;
    // 128 threads x 8 iters. i = tid + j*128: row = i>>3, c16 = i&7.
    const int lrow = tid >> 3;           // 0..15 (+ j*16)
    const int lc16 = tid & 7;

    // Fragment lane byte-offsets within a stage matrix.
    const uint32_t aoff = (uint32_t)((wm + (lid & 15)) * ROWB + (lid >> 4) * 16);
    const uint32_t boff = (uint32_t)((wn + (lid & 7) + ((lid >> 4) & 1) * 8) * ROWB
                                     + ((lid >> 3) & 1) * 16);

    float acc[4][8][4];
#pragma unroll
    for (int mt = 0; mt < 4; mt++)
#pragma unroll
        for (int nt = 0; nt < 8; nt++)
#pragma unroll
            for (int e = 0; e < 4; e++) acc[mt][nt][e] = 0.f;

    const int NC = K >> 6;   // K/64

    auto load_stage = [&](int s, int c) {
        const uint32_t abase = sbase + s * PAIR_BYTES;
        const uint32_t bbase = abase + STAGE_BYTES;
        const int kb = c * BKH;
#pragma unroll
        for (int j = 0; j < 8; j++) {
            const int row = j * 16 + lrow;
            const uint32_t soff = (uint32_t)(row * ROWB + lc16 * 16);
            cp16(abase + soff, A + (size_t)(m0 + row) * K + kb + lc16 * 8);
            cp16(bbase + soff, B + (size_t)(n0 + row) * K + kb + lc16 * 8);
        }
    };

    load_stage(0, 0);
    cp_commit();
    load_stage(1, 1);
    cp_commit();

    for (int c = 0; c < NC; c++) {
        cp_wait<1>();
        __syncthreads();

        if (c + 2 < NC) load_stage((c + 2) % NSTAGE, c + 2);
        cp_commit();

        const uint32_t abase = sbase + (c % NSTAGE) * PAIR_BYTES;
        const uint32_t bbase = abase + STAGE_BYTES;

#pragma unroll
        for (int kk = 0; kk < BKH; kk += 16) {
            uint32_t af[4][4];
            uint32_t bf[8][2];
#pragma unroll
            for (int mt = 0; mt < 4; mt++)
                ldsm4(af[mt], abase + aoff + (uint32_t)(mt * 16 * ROWB + kk * 2));
#pragma unroll
            for (int p = 0; p < 4; p++)
                ldsm4(&bf[2 * p][0], bbase + boff + (uint32_t)(p * 16 * ROWB + kk * 2));
#pragma unroll
            for (int mt = 0; mt < 4; mt++)
#pragma unroll
                for (int nt = 0; nt < 8; nt++)
                    mma_f16(acc[mt][nt], af[mt], bf[nt]);
        }
    }

    // Epilogue
#pragma unroll
    for (int mt = 0; mt < 4; mt++) {
        const int r = m0 + wm + mt * 16 + g;
#pragma unroll
        for (int nt = 0; nt < 8; nt++) {
            const int ccol = n0 + wn + nt * 8 + tig * 2;
            float b0v = 0.f, b1v = 0.f;
            if (bias) { b0v = __ldg(bias + ccol); b1v = __ldg(bias + ccol + 1); }
            float v0 = acc[mt][nt][0] + b0v;
            float v1 = acc[mt][nt][1] + b1v;
            float v2 = acc[mt][nt][2] + b0v;
            float v3 = acc[mt][nt][3] + b1v;
            if constexpr (sizeof(OutT) == 2) {
                __half2 h01 = __floats2half2_rn(v0, v1);
                __half2 h23 = __floats2half2_rn(v2, v3);
                *(__half2*)((__half*)C + (size_t)r * N + ccol) = h01;
                *(__half2*)((__half*)C + (size_t)(r + 8) * N + ccol) = h23;
            } else {
                *(float2*)((float*)C + (size_t)r * N + ccol) = make_float2(v0, v1);
                *(float2*)((float*)C + (size_t)(r + 8) * N + ccol) = make_float2(v2, v3);
            }
        }
    }
}

// ---------------------------------------------------------------------------
// Attention: one block per (sequence, head). fp16 in/out, fp32 math.
// ---------------------------------------------------------------------------
__global__ __launch_bounds__(128) void attn_kernel(
    const __half* __restrict__ qkv, __half* __restrict__ o)
{
    const int nh = blockIdx.x;
    const int head = nh & (NHEADS - 1);
    const int seq = nh >> 4;
    const int w_ = seq % WW;
    const int h_ = (seq / WW) % HH;
    const int b_ = seq / (WW * HH);
    const int base = ((b_ * TT) * HH + h_) * WW + w_;

    __shared__ float Q[32][65];
    __shared__ float K[32][65];
    __shared__ float V[32][65];
    __shared__ float S[32][33];

    const int tid = threadIdx.x;

    for (int idx = tid; idx < 32 * 32; idx += 128) {
        int t = idx >> 5;
        int d2 = idx & 31;
        size_t off2 = ((size_t)(base + t * TOK_TSTRIDE) * E3 + head * HDIM) / 2 + d2;
        const __half2* q2 = (const __half2*)qkv;
        float2 qv = __half22float2(q2[off2]);
        float2 kv = __half22float2(q2[off2 + NHEADS * HDIM / 2]);
        float2 vv = __half22float2(q2[off2 + NHEADS * HDIM]);
        Q[t][d2 * 2] = qv.x; Q[t][d2 * 2 + 1] = qv.y;
        K[t][d2 * 2] = kv.x; K[t][d2 * 2 + 1] = kv.y;
        V[t][d2 * 2] = vv.x; V[t][d2 * 2 + 1] = vv.y;
    }
    __syncthreads();

    const float LOG2_10000_OVER_16 = 13.287712379549449f / 16.0f;
    for (int idx = tid; idx < 32 * (ROTD / 2); idx += 128) {
        int t = idx >> 4;
        int j = idx & 15;
        float freq = exp2f(-(float)j * LOG2_10000_OVER_16);
        float ang = (float)t * freq;
        float c = cosf(ang), s = sinf(ang);
        float q0 = Q[t][2 * j], q1 = Q[t][2 * j + 1];
        Q[t][2 * j]     = q0 * c - q1 * s;
        Q[t][2 * j + 1] = q1 * c + q0 * s;
        float k0 = K[t][2 * j], k1 = K[t][2 * j + 1];
        K[t][2 * j]     = k0 * c - k1 * s;
        K[t][2 * j + 1] = k1 * c + k0 * s;
    }
    __syncthreads();

    // Scores: 2(tq) x 4(tk) per thread; skip fully-masked blocks
    {
        const int tq0 = (tid >> 3) * 2;
        const int tk0 = (tid & 7) * 4;
        if (tk0 <= tq0 + 1) {
            float s0[4] = {0.f, 0.f, 0.f, 0.f};
            float s1[4] = {0.f, 0.f, 0.f, 0.f};
#pragma unroll 8
            for (int d = 0; d < 64; d++) {
                float q0 = Q[tq0][d], q1 = Q[tq0 + 1][d];
#pragma unroll
                for (int j = 0; j < 4; j++) {
                    float kv = K[tk0 + j][d];
                    s0[j] = fmaf(q0, kv, s0[j]);
                    s1[j] = fmaf(q1, kv, s1[j]);
                }
            }
#pragma unroll
            for (int j = 0; j < 4; j++) {
                S[tq0][tk0 + j]     = s0[j] * 0.125f;
                S[tq0 + 1][tk0 + j] = s1[j] * 0.125f;
            }
        }
    }
    __syncthreads();

    if (tid < 32) {
        int row = tid;
        float m = -1e30f;
        for (int k = 0; k <= row; k++) m = fmaxf(m, S[row][k]);
        float sum = 0.f;
        for (int k = 0; k <= row; k++) {
            float e = __expf(S[row][k] - m);
            S[row][k] = e;
            sum += e;
        }
        float inv = 1.0f / sum;
        for (int k = 0; k < 32; k++)
            S[row][k] = (k <= row) ? S[row][k] * inv : 0.f;
    }
    __syncthreads();

    // O = P V: 2(t) x 8(d) per thread, causal k bound; write fp16
    {
        const int t0 = (tid >> 3) * 2;
        const int d0 = (tid & 7) * 8;
        float a0[8], a1[8];
#pragma unroll
        for (int j = 0; j < 8; j++) { a0[j] = 0.f; a1[j] = 0.f; }
        const int kmax = t0 + 1;
        for (int k = 0; k <= kmax; k++) {
            float p0 = S[t0][k], p1 = S[t0 + 1][k];
#pragma unroll
            for (int j = 0; j < 8; j++) {
                float vv = V[k][d0 + j];
                a0[j] = fmaf(p0, vv, a0[j]);
                a1[j] = fmaf(p1, vv, a1[j]);
            }
        }
        __half* orow0 = o + (size_t)(base + t0 * TOK_TSTRIDE) * DIMD + head * HDIM + d0;
        __half* orow1 = o + (size_t)(base + (t0 + 1) * TOK_TSTRIDE) * DIMD + head * HDIM + d0;
#pragma unroll
        for (int j = 0; j < 4; j++) {
            ((__half2*)orow0)[j] = __floats2half2_rn(a0[2 * j], a0[2 * j + 1]);
            ((__half2*)orow1)[j] = __floats2half2_rn(a1[2 * j], a1[2 * j + 1]);
        }
    }
}

// ---------------------------------------------------------------------------
// Launch
// ---------------------------------------------------------------------------
extern "C" void kernel_launch(void* const* d_in, const int* in_sizes, int n_in,
                              void* d_out, int out_size)
{
    const float* x     = (const float*)d_in[0];   // [NTOK, 1024]
    const float* w_qkv = (const float*)d_in[1];   // [3072, 1024]
    const float* w_out = (const float*)d_in[2];   // [1024, 1024]
    const float* b_out = (const float*)d_in[3];   // [1024]
    float* out = (float*)d_out;                   // [NTOK, 1024]

    __half* qkv; __half* o;
    __half* xt; __half* wqt; __half* wot;
    cudaGetSymbolAddress((void**)&qkv, g_qkv);
    cudaGetSymbolAddress((void**)&o,   g_o);
    cudaGetSymbolAddress((void**)&xt,  g_xt);
    cudaGetSymbolAddress((void**)&wqt, g_wqt);
    cudaGetSymbolAddress((void**)&wot, g_wot);

    cudaFuncSetAttribute(gemm_f16<__half>, cudaFuncAttributeMaxDynamicSharedMemorySize, GSMEM_BYTES);
    cudaFuncSetAttribute(gemm_f16<float>,  cudaFuncAttributeMaxDynamicSharedMemorySize, GSMEM_BYTES);

    // 0) Convert inputs to fp16 (rn)
    {
        int n4 = NTOK * DIMD / 4;
        cvt_f16<<<(n4 + 255) / 256, 256>>>((const float4*)x, (uint2*)xt, n4);
        n4 = E3 * DIMD / 4;
        cvt_f16<<<(n4 + 255) / 256, 256>>>((const float4*)w_qkv, (uint2*)wqt, n4);
        n4 = DIMD * DIMD / 4;
        cvt_f16<<<(n4 + 255) / 256, 256>>>((const float4*)w_out, (uint2*)wot, n4);
    }

    // 1) QKV projection -> fp16 qkv
    {
        dim3 grid(E3 / 128, NTOK / 128);
        gemm_f16<__half><<<grid, 128, GSMEM_BYTES>>>(xt, wqt, nullptr, qkv, NTOK, E3, DIMD);
    }

    // 2) Attention (fp16 in/out)
    {
        int nblocks = (BB * HH * WW) * NHEADS;
        attn_kernel<<<nblocks, 128>>>(qkv, o);
    }

    // 3) Output projection -> fp32 out (+bias)
    {
        dim3 grid(DIMD / 128, NTOK / 128);
        gemm_f16<float><<<grid, 128, GSMEM_BYTES>>>(o, wot, b_out, out, NTOK, DIMD, DIMD);
    }
}

// round 16
// speedup vs baseline: 1.9430x; 1.0739x over previous
#include <cuda_runtime.h>
#include <cuda_fp16.h>
#include <cstdint>

// Problem constants
#define DIMD 1024
#define NHEADS 16
#define HDIM 64
#define ROTD 32
#define BB 2
#define TT 32
#define HH 18
#define WW 32
#define NTOK (BB*TT*HH*WW)        // 36864
#define E3 (3*NHEADS*HDIM)        // 3072
#define TOK_TSTRIDE (HH*WW)       // 576

// Scratch (__device__ globals; allocation-free rule)
__device__ __half g_qkv[(size_t)NTOK * E3];     // fp16 qkv
__device__ __half g_o[(size_t)NTOK * DIMD];     // attention output fp16
__device__ __half g_xt[(size_t)NTOK * DIMD];    // x fp16
__device__ __half g_wqt[(size_t)E3 * DIMD];     // w_qkv fp16
__device__ __half g_wot[(size_t)DIMD * DIMD];   // w_out fp16

// ---------------------------------------------------------------------------
// Helpers
// ---------------------------------------------------------------------------
__device__ __forceinline__ uint32_t smem_u32(const void* p) {
    uint32_t a;
    asm("{ .reg .u64 t; cvta.to.shared.u64 t, %1; cvt.u32.u64 %0, t; }" : "=r"(a) : "l"(p));
    return a;
}
__device__ __forceinline__ void cp16(uint32_t saddr, const void* gaddr) {
    asm volatile("cp.async.cg.shared.global [%0], [%1], 16;" :: "r"(saddr), "l"(gaddr));
}
__device__ __forceinline__ void cp_commit() {
    asm volatile("cp.async.commit_group;" ::: "memory");
}
template <int N>
__device__ __forceinline__ void cp_wait() {
    asm volatile("cp.async.wait_group %0;" :: "n"(N) : "memory");
}
__device__ __forceinline__ void ldsm4(uint32_t* r, uint32_t addr) {
    asm volatile("ldmatrix.sync.aligned.m8n8.x4.shared.b16 {%0,%1,%2,%3}, [%4];"
                 : "=r"(r[0]), "=r"(r[1]), "=r"(r[2]), "=r"(r[3]) : "r"(addr));
}
__device__ __forceinline__ void mma_f16(float c[4],
                                        const uint32_t a[4], const uint32_t b[2]) {
    asm volatile(
        "mma.sync.aligned.m16n8k16.row.col.f32.f16.f16.f32 "
        "{%0,%1,%2,%3}, {%4,%5,%6,%7}, {%8,%9}, {%0,%1,%2,%3};"
        : "+f"(c[0]), "+f"(c[1]), "+f"(c[2]), "+f"(c[3])
        : "r"(a[0]), "r"(a[1]), "r"(a[2]), "r"(a[3]), "r"(b[0]), "r"(b[1]));
}

// ---------------------------------------------------------------------------
// fp32 -> fp16 (rn) elementwise. n in float4 units.
// ---------------------------------------------------------------------------
__global__ __launch_bounds__(256) void cvt_f16(const float4* __restrict__ in,
                                               uint2* __restrict__ out, int n4)
{
    int i = blockIdx.x * 256 + threadIdx.x;
    if (i < n4) {
        float4 v = in[i];
        __half2 h0 = __floats2half2_rn(v.x, v.y);
        __half2 h1 = __floats2half2_rn(v.z, v.w);
        uint2 o;
        o.x = *reinterpret_cast<uint32_t*>(&h0);
        o.y = *reinterpret_cast<uint32_t*>(&h1);
        out[i] = o;
    }
}

// ---------------------------------------------------------------------------
// FP16 GEMM (fp32 accum): C[M,N] = A[M,K] * B[N,K]^T (+bias). A,B fp16.
// CTA 128x128, BK=64, 128 threads (4 warps, 64x64 warp tile),
// 3-stage cp.async pipeline, ldmatrix, m16n8k16. Output type templated.
// (At the legacy-mma.sync instruction-rate ceiling; left unchanged.)
// ---------------------------------------------------------------------------
#define NSTAGE 3
#define BKH 64
#define SKH 72
#define ROWB (SKH * 2)                     // 144 bytes
#define STAGE_BYTES (128 * ROWB)           // 18432 per matrix
#define PAIR_BYTES (2 * STAGE_BYTES)       // 36864
#define GSMEM_BYTES (NSTAGE * PAIR_BYTES)  // 110592

template <typename OutT>
__global__ __launch_bounds__(128, 2) void gemm_f16(
    const __half* __restrict__ A, const __half* __restrict__ B,
    const float* __restrict__ bias, OutT* __restrict__ C,
    int M, int N, int K)
{
    extern __shared__ uint32_t sm_[];
    const uint32_t sbase = smem_u32(sm_);

    const int tid = threadIdx.x;
    const int wid = tid >> 5;
    const int lid = tid & 31;
    const int g   = lid >> 2;
    const int tig = lid & 3;
    const int wm  = (wid >> 1) * 64;
    const int wn  = (wid & 1) * 64;
    const int m0 = blockIdx.y * 128;
    const int n0 = blockIdx.x * 128;

    const int lrow = tid >> 3;           // 0..15 (+ j*16)
    const int lc16 = tid & 7;

    const uint32_t aoff = (uint32_t)((wm + (lid & 15)) * ROWB + (lid >> 4) * 16);
    const uint32_t boff = (uint32_t)((wn + (lid & 7) + ((lid >> 4) & 1) * 8) * ROWB
                                     + ((lid >> 3) & 1) * 16);

    float acc[4][8][4];
#pragma unroll
    for (int mt = 0; mt < 4; mt++)
#pragma unroll
        for (int nt = 0; nt < 8; nt++)
#pragma unroll
            for (int e = 0; e < 4; e++) acc[mt][nt][e] = 0.f;

    const int NC = K >> 6;   // K/64

    auto load_stage = [&](int s, int c) {
        const uint32_t abase = sbase + s * PAIR_BYTES;
        const uint32_t bbase = abase + STAGE_BYTES;
        const int kb = c * BKH;
#pragma unroll
        for (int j = 0; j < 8; j++) {
            const int row = j * 16 + lrow;
            const uint32_t soff = (uint32_t)(row * ROWB + lc16 * 16);
            cp16(abase + soff, A + (size_t)(m0 + row) * K + kb + lc16 * 8);
            cp16(bbase + soff, B + (size_t)(n0 + row) * K + kb + lc16 * 8);
        }
    };

    load_stage(0, 0);
    cp_commit();
    load_stage(1, 1);
    cp_commit();

    for (int c = 0; c < NC; c++) {
        cp_wait<1>();
        __syncthreads();

        if (c + 2 < NC) load_stage((c + 2) % NSTAGE, c + 2);
        cp_commit();

        const uint32_t abase = sbase + (c % NSTAGE) * PAIR_BYTES;
        const uint32_t bbase = abase + STAGE_BYTES;

#pragma unroll
        for (int kk = 0; kk < BKH; kk += 16) {
            uint32_t af[4][4];
            uint32_t bf[8][2];
#pragma unroll
            for (int mt = 0; mt < 4; mt++)
                ldsm4(af[mt], abase + aoff + (uint32_t)(mt * 16 * ROWB + kk * 2));
#pragma unroll
            for (int p = 0; p < 4; p++)
                ldsm4(&bf[2 * p][0], bbase + boff + (uint32_t)(p * 16 * ROWB + kk * 2));
#pragma unroll
            for (int mt = 0; mt < 4; mt++)
#pragma unroll
                for (int nt = 0; nt < 8; nt++)
                    mma_f16(acc[mt][nt], af[mt], bf[nt]);
        }
    }

    // Epilogue
#pragma unroll
    for (int mt = 0; mt < 4; mt++) {
        const int r = m0 + wm + mt * 16 + g;
#pragma unroll
        for (int nt = 0; nt < 8; nt++) {
            const int ccol = n0 + wn + nt * 8 + tig * 2;
            float b0v = 0.f, b1v = 0.f;
            if (bias) { b0v = __ldg(bias + ccol); b1v = __ldg(bias + ccol + 1); }
            float v0 = acc[mt][nt][0] + b0v;
            float v1 = acc[mt][nt][1] + b1v;
            float v2 = acc[mt][nt][2] + b0v;
            float v3 = acc[mt][nt][3] + b1v;
            if constexpr (sizeof(OutT) == 2) {
                __half2 h01 = __floats2half2_rn(v0, v1);
                __half2 h23 = __floats2half2_rn(v2, v3);
                *(__half2*)((__half*)C + (size_t)r * N + ccol) = h01;
                *(__half2*)((__half*)C + (size_t)(r + 8) * N + ccol) = h23;
            } else {
                *(float2*)((float*)C + (size_t)r * N + ccol) = make_float2(v0, v1);
                *(float2*)((float*)C + (size_t)(r + 8) * N + ccol) = make_float2(v2, v3);
            }
        }
    }
}

// ---------------------------------------------------------------------------
// Attention: one block per (sequence, head).
// fp16 smem (17 KB -> ~13 CTAs/SM), parallel softmax (4 lanes/row, shfl),
// fp32 math throughout.
// ---------------------------------------------------------------------------
__global__ __launch_bounds__(128) void attn_kernel(
    const __half* __restrict__ qkv, __half* __restrict__ o)
{
    const int nh = blockIdx.x;
    const int head = nh & (NHEADS - 1);
    const int seq = nh >> 4;
    const int w_ = seq % WW;
    const int h_ = (seq / WW) % HH;
    const int b_ = seq / (WW * HH);
    const int base = ((b_ * TT) * HH + h_) * WW + w_;

    __shared__ __half2 Qh[32][33];   // stride 33 half2 -> bank (row+d2)%32
    __shared__ __half2 Kh[32][33];
    __shared__ __half2 Vh[32][33];
    __shared__ float S[32][33];

    const int tid = threadIdx.x;

    // Load Q/K/V: 32 rows x 8 uint4-chunks (4 half2 each) per matrix
    for (int idx = tid; idx < 256; idx += 128) {
        const int t = idx >> 3;
        const int c4 = idx & 7;                    // uint4 chunk (8 halves)
        const __half* gp = qkv + (size_t)(base + t * TOK_TSTRIDE) * E3
                               + head * HDIM + c4 * 8;
        uint4 q = *(const uint4*)gp;
        uint4 k = *(const uint4*)(gp + NHEADS * HDIM);
        uint4 v = *(const uint4*)(gp + 2 * NHEADS * HDIM);
        __half2* qd = &Qh[t][c4 * 4];
        __half2* kd = &Kh[t][c4 * 4];
        __half2* vd = &Vh[t][c4 * 4];
        ((uint32_t*)qd)[0] = q.x; ((uint32_t*)qd)[1] = q.y;
        ((uint32_t*)qd)[2] = q.z; ((uint32_t*)qd)[3] = q.w;
        ((uint32_t*)kd)[0] = k.x; ((uint32_t*)kd)[1] = k.y;
        ((uint32_t*)kd)[2] = k.z; ((uint32_t*)kd)[3] = k.w;
        ((uint32_t*)vd)[0] = v.x; ((uint32_t*)vd)[1] = v.y;
        ((uint32_t*)vd)[2] = v.z; ((uint32_t*)vd)[3] = v.w;
    }
    __syncthreads();

    // RoPE: interleaved pairs == half2 lanes j<16
    const float LOG2_10000_OVER_16 = 13.287712379549449f / 16.0f;
    for (int idx = tid; idx < 32 * 16; idx += 128) {
        const int t = idx >> 4;
        const int j = idx & 15;
        float freq = exp2f(-(float)j * LOG2_10000_OVER_16);
        float ang = (float)t * freq;
        float c = cosf(ang), s = sinf(ang);
        float2 q = __half22float2(Qh[t][j]);
        float2 k = __half22float2(Kh[t][j]);
        Qh[t][j] = __floats2half2_rn(q.x * c - q.y * s, q.y * c + q.x * s);
        Kh[t][j] = __floats2half2_rn(k.x * c - k.y * s, k.y * c + k.x * s);
    }
    __syncthreads();

    // Scores: 2(tq) x 4(tk) per thread; skip fully-masked blocks
    {
        const int tq0 = (tid >> 3) * 2;
        const int tk0 = (tid & 7) * 4;
        if (tk0 <= tq0 + 1) {
            float s0[4] = {0.f, 0.f, 0.f, 0.f};
            float s1[4] = {0.f, 0.f, 0.f, 0.f};
#pragma unroll 8
            for (int d2 = 0; d2 < 32; d2++) {
                float2 qa = __half22float2(Qh[tq0][d2]);
                float2 qb = __half22float2(Qh[tq0 + 1][d2]);
#pragma unroll
                for (int j = 0; j < 4; j++) {
                    float2 kv = __half22float2(Kh[tk0 + j][d2]);
                    s0[j] = fmaf(qa.x, kv.x, fmaf(qa.y, kv.y, s0[j]));
                    s1[j] = fmaf(qb.x, kv.x, fmaf(qb.y, kv.y, s1[j]));
                }
            }
#pragma unroll
            for (int j = 0; j < 4; j++) {
                S[tq0][tk0 + j]     = s0[j] * 0.125f;
                S[tq0 + 1][tk0 + j] = s1[j] * 0.125f;
            }
        }
    }
    __syncthreads();

    // Parallel causal softmax: 32 rows x 4 lanes; lane q owns cols q*8..q*8+7
    {
        const int row = tid >> 2;
        const int q   = tid & 3;
        float e[8];
        float m = -1e30f;
#pragma unroll
        for (int i = 0; i < 8; i++) {
            const int k = q * 8 + i;
            e[i] = (k <= row) ? S[row][k] : -1e30f;
            m = fmaxf(m, e[i]);
        }
        m = fmaxf(m, __shfl_xor_sync(0xffffffffu, m, 1));
        m = fmaxf(m, __shfl_xor_sync(0xffffffffu, m, 2));
        float sum = 0.f;
#pragma unroll
        for (int i = 0; i < 8; i++) {
            const int k = q * 8 + i;
            e[i] = (k <= row) ? __expf(e[i] - m) : 0.f;
            sum += e[i];
        }
        sum += __shfl_xor_sync(0xffffffffu, sum, 1);
        sum += __shfl_xor_sync(0xffffffffu, sum, 2);
        const float inv = 1.0f / sum;
#pragma unroll
        for (int i = 0; i < 8; i++)
            S[row][q * 8 + i] = e[i] * inv;
    }
    __syncthreads();

    // O = P V: 2(t) x 8(d) per thread, causal k bound; write fp16
    {
        const int t0  = (tid >> 3) * 2;
        const int d2q = (tid & 7) * 4;    // half2 base along dim
        float2 a0[4], a1[4];
#pragma unroll
        for (int j = 0; j < 4; j++) { a0[j] = make_float2(0.f, 0.f); a1[j] = make_float2(0.f, 0.f); }
        const int kmax = t0 + 1;
        for (int k = 0; k <= kmax; k++) {
            const float p0 = S[t0][k], p1 = S[t0 + 1][k];
#pragma unroll
            for (int j = 0; j < 4; j++) {
                float2 vv = __half22float2(Vh[k][d2q + j]);
                a0[j].x = fmaf(p0, vv.x, a0[j].x); a0[j].y = fmaf(p0, vv.y, a0[j].y);
                a1[j].x = fmaf(p1, vv.x, a1[j].x); a1[j].y = fmaf(p1, vv.y, a1[j].y);
            }
        }
        __half2* orow0 = (__half2*)(o + (size_t)(base + t0 * TOK_TSTRIDE) * DIMD
                                      + head * HDIM) + d2q;
        __half2* orow1 = (__half2*)(o + (size_t)(base + (t0 + 1) * TOK_TSTRIDE) * DIMD
                                      + head * HDIM) + d2q;
#pragma unroll
        for (int j = 0; j < 4; j++) {
            orow0[j] = __floats2half2_rn(a0[j].x, a0[j].y);
            orow1[j] = __floats2half2_rn(a1[j].x, a1[j].y);
        }
    }
}

// ---------------------------------------------------------------------------
// Launch
// ---------------------------------------------------------------------------
extern "C" void kernel_launch(void* const* d_in, const int* in_sizes, int n_in,
                              void* d_out, int out_size)
{
    const float* x     = (const float*)d_in[0];   // [NTOK, 1024]
    const float* w_qkv = (const float*)d_in[1];   // [3072, 1024]
    const float* w_out = (const float*)d_in[2];   // [1024, 1024]
    const float* b_out = (const float*)d_in[3];   // [1024]
    float* out = (float*)d_out;                   // [NTOK, 1024]

    __half* qkv; __half* o;
    __half* xt; __half* wqt; __half* wot;
    cudaGetSymbolAddress((void**)&qkv, g_qkv);
    cudaGetSymbolAddress((void**)&o,   g_o);
    cudaGetSymbolAddress((void**)&xt,  g_xt);
    cudaGetSymbolAddress((void**)&wqt, g_wqt);
    cudaGetSymbolAddress((void**)&wot, g_wot);

    cudaFuncSetAttribute(gemm_f16<__half>, cudaFuncAttributeMaxDynamicSharedMemorySize, GSMEM_BYTES);
    cudaFuncSetAttribute(gemm_f16<float>,  cudaFuncAttributeMaxDynamicSharedMemorySize, GSMEM_BYTES);

    // 0) Convert inputs to fp16 (rn)
    {
        int n4 = NTOK * DIMD / 4;
        cvt_f16<<<(n4 + 255) / 256, 256>>>((const float4*)x, (uint2*)xt, n4);
        n4 = E3 * DIMD / 4;
        cvt_f16<<<(n4 + 255) / 256, 256>>>((const float4*)w_qkv, (uint2*)wqt, n4);
        n4 = DIMD * DIMD / 4;
        cvt_f16<<<(n4 + 255) / 256, 256>>>((const float4*)w_out, (uint2*)wot, n4);
    }

    // 1) QKV projection -> fp16 qkv
    {
        dim3 grid(E3 / 128, NTOK / 128);
        gemm_f16<__half><<<grid, 128, GSMEM_BYTES>>>(xt, wqt, nullptr, qkv, NTOK, E3, DIMD);
    }

    // 2) Attention (fp16 in/out)
    {
        int nblocks = (BB * HH * WW) * NHEADS;
        attn_kernel<<<nblocks, 128>>>(qkv, o);
    }

    // 3) Output projection -> fp32 out (+bias)
    {
        dim3 grid(DIMD / 128, NTOK / 128);
        gemm_f16<float><<<grid, 128, GSMEM_BYTES>>>(o, wot, b_out, out, NTOK, DIMD, DIMD);
    }
}